// round 1
// baseline (speedup 1.0000x reference)
#include <cuda_runtime.h>
#include <math.h>

#define BB 4
#define CC 64
#define HH 256
#define WW 256
#define WF 129
#define HWF (HH*WF)            // 33024
#define NPIX (BB*CC*HWF)       // 8454144
#define H3 768
#define W3 387
#define EPLANE (H3*W3)         // 297216
#define FPAD 261

// ---------------- scratch (static device globals; no allocation) ----------------
__device__ float2 g_XF[NPIX];                 // spectrum / combined complex
__device__ float  g_amp[NPIX];
__device__ float  g_pha[NPIX];
__device__ float  g_a3[NPIX];
__device__ float  g_p3[NPIX];
__device__ float  g_a1[NPIX];
__device__ float  g_p1[NPIX];
__device__ float  g_offs[BB*18*HWF];
__device__ int4   g_sidx[BB*HWF*9];
__device__ float4 g_sw[BB*HWF*9];
__device__ float  g_E[(size_t)BB*CC*EPLANE]; // expanded sampled map
__device__ float  g_xr[(size_t)BB*CC*HH*WW];

// ---------------- FFT-256, 128 threads, shared array of 256 float2 ----------------
__device__ __forceinline__ void fft256_128t(float2* s, int t, float sign) {
    // bit reversal (each index visited once; pair swapped by smaller index)
#pragma unroll
    for (int kk = 0; kk < 2; kk++) {
        int i = t + (kk << 7);
        int j = __brev(i) >> 24;
        if (i < j) { float2 a = s[i]; s[i] = s[j]; s[j] = a; }
    }
    __syncthreads();
    for (int len = 2; len <= 256; len <<= 1) {
        int half = len >> 1;
        int g = t / half;
        int p = t - g * half;
        int i0 = g * len + p;
        int i1 = i0 + half;
        float ang = sign * 6.28318530717958647692f * (float)p / (float)len;
        float cw, sw;
        sincosf(ang, &sw, &cw);
        float2 a = s[i0], b = s[i1];
        float2 wb = make_float2(cw * b.x - sw * b.y, cw * b.y + sw * b.x);
        s[i0] = make_float2(a.x + wb.x, a.y + wb.y);
        s[i1] = make_float2(a.x - wb.x, a.y - wb.y);
        __syncthreads();
    }
}

// Row forward rFFT: x[b,c,h,0..255] -> g_XF[b,c,h,0..128]
__global__ void fft_row_fwd(const float* __restrict__ x) {
    __shared__ float2 s[256];
    int h  = blockIdx.x & 255;
    int bc = blockIdx.x >> 8;
    int t  = threadIdx.x;
    const float* row = x + ((size_t)bc * 256 + h) * 256;
    s[t]       = make_float2(row[t], 0.f);
    s[t + 128] = make_float2(row[t + 128], 0.f);
    __syncthreads();
    fft256_128t(s, t, -1.f);
    size_t ob = ((size_t)bc * 256 + h) * WF;
    g_XF[ob + t] = s[t];
    if (t == 0) g_XF[ob + 128] = s[128];
}

// Column FFT (16 columns per block). dir=0: forward, emits amp/pha. dir=1: inverse in-place on g_XF.
__global__ void fft_col_kernel(int dir) {
    __shared__ float2 S[16 * FPAD];
    int k0 = blockIdx.x * 16;
    int c = blockIdx.y, b = blockIdx.z;
    int tid = threadIdx.x;
    size_t base = ((size_t)(b * CC + c)) * HH * WF;

    for (int idx = tid; idx < 256 * 16; idx += 256) {
        int h = idx >> 4, kk = idx & 15;
        int k = k0 + kk;
        float2 v = (k < WF) ? g_XF[base + (size_t)h * WF + k] : make_float2(0.f, 0.f);
        S[kk * FPAD + h] = v;
    }
    __syncthreads();

    int f = tid >> 4;     // which FFT
    int l = tid & 15;     // lane within FFT (16 threads per FFT)
    float2* s = &S[f * FPAD];
#pragma unroll
    for (int m = 0; m < 16; m++) {
        int i = l + (m << 4);
        int j = __brev(i) >> 24;
        if (i < j) { float2 a = s[i]; s[i] = s[j]; s[j] = a; }
    }
    __syncthreads();
    float sign = dir ? 1.f : -1.f;
    for (int len = 2; len <= 256; len <<= 1) {
        int half = len >> 1;
#pragma unroll
        for (int m = 0; m < 8; m++) {
            int t = l + (m << 4);
            int g = t / half;
            int p = t - g * half;
            int i0 = g * len + p;
            int i1 = i0 + half;
            float ang = sign * 6.28318530717958647692f * (float)p / (float)len;
            float cw, sw;
            sincosf(ang, &sw, &cw);
            float2 a = s[i0], bv = s[i1];
            float2 wb = make_float2(cw * bv.x - sw * bv.y, cw * bv.y + sw * bv.x);
            s[i0] = make_float2(a.x + wb.x, a.y + wb.y);
            s[i1] = make_float2(a.x - wb.x, a.y - wb.y);
        }
        __syncthreads();
    }

    if (dir == 0) {
        for (int idx = tid; idx < 256 * 16; idx += 256) {
            int h = idx >> 4, kk = idx & 15;
            int k = k0 + kk;
            if (k < WF) {
                float2 v = S[kk * FPAD + h];
                size_t o = base + (size_t)h * WF + k;
                g_amp[o] = sqrtf(v.x * v.x + v.y * v.y);
                g_pha[o] = atan2f(v.y, v.x);
            }
        }
    } else {
        for (int idx = tid; idx < 256 * 16; idx += 256) {
            int h = idx >> 4, kk = idx & 15;
            int k = k0 + kk;
            if (k < WF) g_XF[base + (size_t)h * WF + k] = S[kk * FPAD + h];
        }
    }
}

// Row inverse rFFT + abs -> g_xr
__global__ void ifft_row_kernel() {
    __shared__ float2 s[256];
    int h  = blockIdx.x & 255;
    int bc = blockIdx.x >> 8;
    int t  = threadIdx.x;
    size_t base = ((size_t)bc * 256 + h) * WF;
    s[t] = g_XF[base + t];
    float2 v;
    if (t == 0) v = g_XF[base + 128];
    else { float2 u = g_XF[base + 128 - t]; v = make_float2(u.x, -u.y); }
    s[t + 128] = v;
    __syncthreads();
    fft256_128t(s, t, +1.f);
    const float inv = 1.f / 65536.f;
    float* orow = g_xr + ((size_t)bc * 256 + h) * 256;
    orow[t]       = fabsf(s[t].x * inv);
    orow[t + 128] = fabsf(s[t + 128].x * inv);
}

// ---------------- 3x3 pad-1 conv, 64 -> 18 channels (offset conv) ----------------
__global__ void conv_off_kernel(const float* __restrict__ wp, const float* __restrict__ bp, int srcflag) {
    __shared__ float T[18][19];
    __shared__ float wS[162];
    int w0b = blockIdx.x * 16, h0 = blockIdx.y * 16, b = blockIdx.z;
    const float* src = srcflag ? g_pha : g_amp;
    int tid = threadIdx.x;
    int tx = tid & 15, ty = tid >> 4;
    float acc[18];
#pragma unroll
    for (int o = 0; o < 18; o++) acc[o] = 0.f;

    for (int ic = 0; ic < CC; ic++) {
        __syncthreads();
        const float* P = src + (size_t)(b * CC + ic) * HWF;
        for (int idx = tid; idx < 18 * 18; idx += 256) {
            int r = idx / 18, cc = idx % 18;
            int gh = h0 + r - 1, gw = w0b + cc - 1;
            T[r][cc] = (gh >= 0 && gh < HH && gw >= 0 && gw < WF) ? P[gh * WF + gw] : 0.f;
        }
        if (tid < 162) wS[tid] = wp[((tid / 9) * CC + ic) * 9 + (tid % 9)];
        __syncthreads();
#pragma unroll
        for (int k = 0; k < 9; k++) {
            float v = T[ty + k / 3][tx + k % 3];
#pragma unroll
            for (int o = 0; o < 18; o++) acc[o] += wS[o * 9 + k] * v;
        }
    }
    int h = h0 + ty, w = w0b + tx;
    if (w < WF) {
#pragma unroll
        for (int o = 0; o < 18; o++)
            g_offs[((size_t)(b * 18 + o) * HH + h) * WF + w] = acc[o] + bp[o];
    }
}

// ---------------- bilinear sampling parameters (shared across channels) ----------------
__device__ __forceinline__ int padidx(float qx, float qy) {
    int X = (int)qx, Y = (int)qy;
    if (X >= 1 && X <= 256 && Y >= 1 && Y <= 129) return (X - 1) * WF + (Y - 1);
    return -1;
}

__global__ void sample_params_kernel() {
    int idx = blockIdx.x * blockDim.x + threadIdx.x;
    if (idx >= BB * HWF * 9) return;
    int n = idx % 9;
    int rest = idx / 9;
    int w = rest % WF; rest /= WF;
    int h = rest % HH;
    int b = rest / HH;
    int i = n / 3, j = n % 3;
    float offx = g_offs[((size_t)(b * 18 + n) * HH + h) * WF + w];
    float offy = g_offs[((size_t)(b * 18 + n + 9) * HH + h) * WF + w];
    float px = (float)(h + 1) + (float)(i - 1) + offx;
    float py = (float)(w + 1) + (float)(j - 1) + offy;
    float qx = floorf(px), qy = floorf(py);
    const float HMax = 257.f, WMax = 130.f;
    float qltx = fminf(fmaxf(qx, 0.f), HMax);
    float qlty = fminf(fmaxf(qy, 0.f), WMax);
    float qrbx = fminf(fmaxf(qx + 1.f, 0.f), HMax);
    float qrby = fminf(fmaxf(qy + 1.f, 0.f), WMax);
    float cpx  = fminf(fmaxf(px, 0.f), HMax);
    float cpy  = fminf(fmaxf(py, 0.f), WMax);
    float glt = (1.f + (qltx - cpx)) * (1.f + (qlty - cpy));
    float grb = (1.f - (qrbx - cpx)) * (1.f - (qrby - cpy));
    float glb = (1.f + (qltx - cpx)) * (1.f - (qrby - cpy));
    float grt = (1.f - (qrbx - cpx)) * (1.f + (qlty - cpy));
    g_sidx[idx] = make_int4(padidx(qltx, qlty), padidx(qrbx, qrby),
                            padidx(qltx, qrby), padidx(qrbx, qlty));
    g_sw[idx] = make_float4(glt, grb, glb, grt);
}

// ---------------- gather into expanded map E[b,c,3h+i,3w+j] ----------------
__global__ void gather_kernel(int srcflag) {
    size_t idx = (size_t)blockIdx.x * 256 + threadIdx.x;
    if (idx >= (size_t)NPIX) return;
    int w = (int)(idx % WF);
    size_t r = idx / WF;
    int h = (int)(r % HH); r /= HH;
    int c = (int)(r % CC);
    int b = (int)(r / CC);
    const float* P = (srcflag ? g_pha : g_amp) + (size_t)(b * CC + c) * HWF;
    float* Ep = g_E + (size_t)(b * CC + c) * EPLANE;
    size_t pb = (((size_t)b * HH + h) * WF + w) * 9;
#pragma unroll
    for (int n = 0; n < 9; n++) {
        int4 id = g_sidx[pb + n];
        float4 g = g_sw[pb + n];
        float v = 0.f;
        if (id.x >= 0) v += g.x * __ldg(P + id.x);
        if (id.y >= 0) v += g.y * __ldg(P + id.y);
        if (id.z >= 0) v += g.z * __ldg(P + id.z);
        if (id.w >= 0) v += g.w * __ldg(P + id.w);
        Ep[(size_t)(3 * h + n / 3) * W3 + (3 * w + n % 3)] = v;
    }
}

// ---------------- 3x3 stride-3 pad-1 conv on expanded map, 64 -> 64 ----------------
__global__ void conv_s3_kernel(const float* __restrict__ wc, int dstflag) {
    __shared__ float ES[48][49];
    __shared__ float wS[72];
    int ow0 = blockIdx.x * 16, oh0 = blockIdx.y * 16;
    int bz = blockIdx.z;
    int ocg = bz & 7;
    int b = bz >> 3;
    int tid = threadIdx.x;
    int tx = tid & 15, ty = tid >> 4;
    float acc[8] = {0.f, 0.f, 0.f, 0.f, 0.f, 0.f, 0.f, 0.f};
    int r_base = 3 * oh0 - 1, c_base = 3 * ow0 - 1;

    for (int ic = 0; ic < CC; ic++) {
        __syncthreads();
        const float* Ep = g_E + (size_t)(b * CC + ic) * EPLANE;
        for (int idx = tid; idx < 48 * 48; idx += 256) {
            int r = idx / 48, cc = idx % 48;
            int gr = r_base + r, gc = c_base + cc;
            ES[r][cc] = (gr >= 0 && gr < H3 && gc >= 0 && gc < W3)
                        ? Ep[(size_t)gr * W3 + gc] : 0.f;
        }
        if (tid < 72) wS[tid] = wc[((ocg * 8 + tid / 9) * CC + ic) * 9 + (tid % 9)];
        __syncthreads();
#pragma unroll
        for (int k = 0; k < 9; k++) {
            float v = ES[3 * ty + k / 3][3 * tx + k % 3];
#pragma unroll
            for (int j = 0; j < 8; j++) acc[j] += wS[j * 9 + k] * v;
        }
    }
    int oh = oh0 + ty, ow = ow0 + tx;
    if (ow < WF) {
        float* dst = dstflag ? g_p3 : g_a3;
#pragma unroll
        for (int j = 0; j < 8; j++)
            dst[((size_t)(b * CC + ocg * 8 + j) * HH + oh) * WF + ow] = acc[j];
    }
}

// ---------------- 1x1 conv, 64 -> 64 ----------------
__global__ void conv1x1_kernel(const float* __restrict__ w1, const float* __restrict__ b1,
                               int srcflag, int dstflag) {
    __shared__ float XS[64][33];
    __shared__ float WT[64][65];
    int p0 = blockIdx.x * 32;
    int b = blockIdx.y;
    int tid = threadIdx.x;
    const float* src = (srcflag ? g_pha : g_amp) + (size_t)b * CC * HWF;
    for (int idx = tid; idx < 2048; idx += 256) {
        int c = idx >> 5, p = idx & 31;
        XS[c][p] = src[(size_t)c * HWF + p0 + p];
    }
    for (int idx = tid; idx < 4096; idx += 256) {
        int oc = idx >> 6, k = idx & 63;
        WT[k][oc] = w1[idx];
    }
    __syncthreads();
    int px = tid & 31, ocg = tid >> 5;
    float acc[8] = {0.f, 0.f, 0.f, 0.f, 0.f, 0.f, 0.f, 0.f};
    for (int k = 0; k < 64; k++) {
        float xv = XS[k][px];
#pragma unroll
        for (int j = 0; j < 8; j++) acc[j] += WT[k][ocg + 8 * j] * xv;
    }
    float* dst = (dstflag ? g_p1 : g_a1) + (size_t)b * CC * HWF;
#pragma unroll
    for (int j = 0; j < 8; j++) {
        int oc = ocg + 8 * j;
        dst[(size_t)oc * HWF + p0 + px] = acc[j] + b1[oc];
    }
}

// ---------------- elementwise recombine into complex spectrum ----------------
__global__ void combine_kernel() {
    size_t idx = (size_t)blockIdx.x * 256 + threadIdx.x;
    if (idx >= (size_t)NPIX) return;
    float a1 = g_a1[idx], p1 = g_p1[idx];
    float a3 = g_a3[idx], p3 = g_p3[idx];
    float s1, c1, s3, c3;
    sincosf(p1, &s1, &c1);
    sincosf(p3, &s3, &c3);
    g_XF[idx] = make_float2(a1 * c3 + a3 * c1 + 3e-8f,
                            a3 * s1 + a1 * s3 + 2e-8f);
}

// ---------------- final 5x5 pad-2 conv, 64 -> 64 ----------------
__global__ void conv5x5_kernel(const float* __restrict__ w0, const float* __restrict__ b0,
                               float* __restrict__ out) {
    __shared__ float T[20][21];
    __shared__ float wS[200];
    int w0b = blockIdx.x * 16, h0 = blockIdx.y * 16;
    int bz = blockIdx.z;
    int ocg = bz & 7;
    int b = bz >> 3;
    int tid = threadIdx.x;
    int tx = tid & 15, ty = tid >> 4;
    float acc[8] = {0.f, 0.f, 0.f, 0.f, 0.f, 0.f, 0.f, 0.f};

    for (int ic = 0; ic < CC; ic++) {
        __syncthreads();
        const float* P = g_xr + (size_t)(b * CC + ic) * HH * WW;
        for (int idx = tid; idx < 400; idx += 256) {
            int r = idx / 20, cc = idx % 20;
            int gh = h0 + r - 2, gw = w0b + cc - 2;
            T[r][cc] = (gh >= 0 && gh < HH && gw >= 0 && gw < WW)
                       ? P[(size_t)gh * WW + gw] : 0.f;
        }
        if (tid < 200) wS[tid] = w0[((ocg * 8 + tid / 25) * CC + ic) * 25 + (tid % 25)];
        __syncthreads();
#pragma unroll
        for (int k = 0; k < 25; k++) {
            float v = T[ty + k / 5][tx + k % 5];
#pragma unroll
            for (int j = 0; j < 8; j++) acc[j] += wS[j * 25 + k] * v;
        }
    }
    int h = h0 + ty, w = w0b + tx;
#pragma unroll
    for (int j = 0; j < 8; j++) {
        int oc = ocg * 8 + j;
        out[((size_t)(b * CC + oc) * HH + h) * WW + w] = acc[j] + b0[oc];
    }
}

// ---------------- launcher ----------------
extern "C" void kernel_launch(void* const* d_in, const int* in_sizes, int n_in,
                              void* d_out, int out_size) {
    (void)in_sizes; (void)n_in; (void)out_size;
    const float* x    = (const float*)d_in[0];
    const float* wp_a = (const float*)d_in[1];
    const float* bp_a = (const float*)d_in[2];
    const float* wc_a = (const float*)d_in[3];
    const float* w1_a = (const float*)d_in[4];
    const float* b1_a = (const float*)d_in[5];
    const float* wp_p = (const float*)d_in[6];
    const float* bp_p = (const float*)d_in[7];
    const float* wc_p = (const float*)d_in[8];
    const float* w1_p = (const float*)d_in[9];
    const float* b1_p = (const float*)d_in[10];
    const float* w0   = (const float*)d_in[11];
    const float* b0   = (const float*)d_in[12];
    float* out = (float*)d_out;

    // forward rfft2 + amp/phase
    fft_row_fwd<<<BB * CC * HH, 128>>>(x);
    fft_col_kernel<<<dim3(9, CC, BB), 256>>>(0);

    // amp branch
    conv_off_kernel<<<dim3(9, 16, BB), 256>>>(wp_a, bp_a, 0);
    sample_params_kernel<<<(BB * HWF * 9 + 255) / 256, 256>>>();
    gather_kernel<<<NPIX / 256, 256>>>(0);
    conv_s3_kernel<<<dim3(9, 16, BB * 8), 256>>>(wc_a, 0);
    conv1x1_kernel<<<dim3(HWF / 32, BB), 256>>>(w1_a, b1_a, 0, 0);

    // pha branch
    conv_off_kernel<<<dim3(9, 16, BB), 256>>>(wp_p, bp_p, 1);
    sample_params_kernel<<<(BB * HWF * 9 + 255) / 256, 256>>>();
    gather_kernel<<<NPIX / 256, 256>>>(1);
    conv_s3_kernel<<<dim3(9, 16, BB * 8), 256>>>(wc_p, 1);
    conv1x1_kernel<<<dim3(HWF / 32, BB), 256>>>(w1_p, b1_p, 1, 1);

    // recombine + inverse transform
    combine_kernel<<<NPIX / 256, 256>>>();
    fft_col_kernel<<<dim3(9, CC, BB), 256>>>(1);
    ifft_row_kernel<<<BB * CC * HH, 128>>>();

    // final 5x5 conv
    conv5x5_kernel<<<dim3(16, 16, BB * 8), 256>>>(w0, b0, out);
}

// round 3
// speedup vs baseline: 1.4001x; 1.4001x over previous
#include <cuda_runtime.h>
#include <math.h>

#define BB 4
#define CC 64
#define HH 256
#define WW 256
#define WF 129
#define HWF (HH*WF)            // 33024
#define NPIX (BB*CC*HWF)       // 8454144
#define H3 768
#define W3 387
#define EPLANE (H3*W3)         // 297216
#define FPAD 261

// ---------------- scratch ----------------
__device__ float2 g_XF[NPIX];
__device__ float  g_amp[NPIX];
__device__ float  g_pha[NPIX];
__device__ float  g_a3[NPIX];
__device__ float  g_p3[NPIX];
__device__ float  g_a1[NPIX];
__device__ float  g_p1[NPIX];
__device__ float  g_offs[BB*18*HWF];
__device__ int4   g_sidx[BB*HWF*9];
__device__ float4 g_sw[BB*HWF*9];
__device__ float  g_E[(size_t)BB*CC*EPLANE];
__device__ float  g_xr[(size_t)BB*CC*HH*WW];
__device__ float2 g_tw[129];

// ---------------- packed f32x2 helpers ----------------
typedef unsigned long long u64;
__device__ __forceinline__ u64 pack2(float lo, float hi) {
    u64 r; asm("mov.b64 %0, {%1, %2};" : "=l"(r) : "f"(lo), "f"(hi)); return r;
}
__device__ __forceinline__ void unpack2(u64 v, float& lo, float& hi) {
    asm("mov.b64 {%0, %1}, %2;" : "=f"(lo), "=f"(hi) : "l"(v));
}
__device__ __forceinline__ void fma2(u64& d, u64 a, u64 b) {
    asm("fma.rn.f32x2 %0, %1, %2, %0;" : "+l"(d) : "l"(a), "l"(b));
}

// ---------------- precise transcendentals (fast-math-proof) ----------------
__device__ __forceinline__ void sincos_acc(float x, float* sp, float* cp) {
    float k = rintf(x * 0.63661977236758134f);
    float r = fmaf(k, -1.5707963705062866f, x);
    r = fmaf(k, 4.37113900018624e-8f, r);
    int q = (int)k;
    float z = r * r;
    float ss = 2.75573192e-6f;
    ss = fmaf(ss, z, -1.98412698e-4f);
    ss = fmaf(ss, z, 8.33333333e-3f);
    ss = fmaf(ss, z, -1.66666667e-1f);
    ss = fmaf(ss * z, r, r);
    float cc = -2.75573192e-7f;
    cc = fmaf(cc, z, 2.48015873e-5f);
    cc = fmaf(cc, z, -1.38888889e-3f);
    cc = fmaf(cc, z, 4.16666667e-2f);
    cc = fmaf(cc, z, -0.5f);
    cc = fmaf(cc, z, 1.0f);
    int qq = q & 3;
    float s_ = (qq & 1) ? cc : ss;
    float c_ = (qq & 1) ? ss : cc;
    if (qq == 1 || qq == 2) c_ = -c_;
    if (qq >= 2) s_ = -s_;
    *sp = s_; *cp = c_;
}

__device__ __forceinline__ float atan2_acc(float y, float x) {
    float ax = fabsf(x), ay = fabsf(y);
    float mx = fmaxf(ax, ay), mn = fminf(ax, ay);
    float t = (mx > 0.f) ? __fdiv_rn(mn, mx) : 0.f;
    float base = 0.f;
    if (t > 0.414213562f) { t = __fdiv_rn(t - 1.f, t + 1.f); base = 0.78539816339744831f; }
    float z = t * t;
    float p = -0.066666667f;
    p = fmaf(p, z,  0.076923077f);
    p = fmaf(p, z, -0.090909091f);
    p = fmaf(p, z,  0.111111111f);
    p = fmaf(p, z, -0.142857143f);
    p = fmaf(p, z,  0.2f);
    p = fmaf(p, z, -0.333333333f);
    float r = fmaf(t * z, p, t) + base;
    if (ay > ax) r = 1.57079632679489662f - r;
    if (x < 0.f) r = 3.14159265358979323f - r;
    return copysignf(r, y);
}

__global__ void twiddle_init() {
    int k = threadIdx.x;
    if (k < 129) {
        double a = -2.0 * 3.14159265358979323846 * (double)k / 256.0;
        float2 v = make_float2((float)cos(a), (float)sin(a));
        if (k == 0) v = make_float2(1.f, 0.f);
        g_tw[k] = v;
    }
}

// ---------------- FFT-256 core (table stores FORWARD twiddles e^{-i2pik/256}) ----------------
// sign = +1 : forward (use table as-is). sign = -1 : inverse (conjugate table).
__device__ __forceinline__ void fft256_tab(float2* s, const float2* tw, int t, float sign) {
#pragma unroll
    for (int kk = 0; kk < 2; kk++) {
        int i = t + (kk << 7);
        int j = __brev(i) >> 24;
        if (i < j) { float2 a = s[i]; s[i] = s[j]; s[j] = a; }
    }
    __syncthreads();
#pragma unroll
    for (int st = 1; st <= 8; st++) {
        int half = 1 << (st - 1);
        int g = t >> (st - 1);
        int p = t & (half - 1);
        int i0 = (g << st) + p;
        int i1 = i0 + half;
        float2 w = tw[p << (8 - st)];
        float wy = sign * w.y;
        float2 a = s[i0], b = s[i1];
        float2 wb = make_float2(w.x * b.x - wy * b.y, w.x * b.y + wy * b.x);
        s[i0] = make_float2(a.x + wb.x, a.y + wb.y);
        s[i1] = make_float2(a.x - wb.x, a.y - wb.y);
        __syncthreads();
    }
}

__global__ void fft_row_fwd(const float* __restrict__ x) {
    __shared__ float2 s[256];
    __shared__ float2 tw[128];
    int h = blockIdx.x & 255, bc = blockIdx.x >> 8, t = threadIdx.x;
    tw[t] = g_tw[t];
    const float* row = x + ((size_t)bc * 256 + h) * 256;
    s[t]       = make_float2(row[t], 0.f);
    s[t + 128] = make_float2(row[t + 128], 0.f);
    __syncthreads();
    fft256_tab(s, tw, t, +1.f);   // forward
    size_t ob = ((size_t)bc * 256 + h) * WF;
    g_XF[ob + t] = s[t];
    if (t == 0) g_XF[ob + 128] = s[128];
}

__global__ void fft_col_kernel(int dir) {
    __shared__ float2 S[16 * FPAD];
    __shared__ float2 tw[128];
    int k0 = blockIdx.x * 16;
    int c = blockIdx.y, b = blockIdx.z;
    int tid = threadIdx.x;
    if (tid < 128) tw[tid] = g_tw[tid];
    size_t base = ((size_t)(b * CC + c)) * HH * WF;

    for (int idx = tid; idx < 256 * 16; idx += 256) {
        int h = idx >> 4, kk = idx & 15;
        int k = k0 + kk;
        float2 v = (k < WF) ? g_XF[base + (size_t)h * WF + k] : make_float2(0.f, 0.f);
        S[kk * FPAD + h] = v;
    }
    __syncthreads();

    int f = tid >> 4;
    int l = tid & 15;
    float2* s = &S[f * FPAD];
#pragma unroll
    for (int m = 0; m < 16; m++) {
        int i = l + (m << 4);
        int j = __brev(i) >> 24;
        if (i < j) { float2 a = s[i]; s[i] = s[j]; s[j] = a; }
    }
    __syncthreads();
    float sign = dir ? -1.f : 1.f;   // dir=0 forward, dir=1 inverse
#pragma unroll
    for (int st = 1; st <= 8; st++) {
        int half = 1 << (st - 1);
#pragma unroll
        for (int m = 0; m < 8; m++) {
            int t = l + (m << 4);
            int g = t >> (st - 1);
            int p = t & (half - 1);
            int i0 = (g << st) + p;
            int i1 = i0 + half;
            float2 w = tw[p << (8 - st)];
            float wy = sign * w.y;
            float2 a = s[i0], bv = s[i1];
            float2 wb = make_float2(w.x * bv.x - wy * bv.y, w.x * bv.y + wy * bv.x);
            s[i0] = make_float2(a.x + wb.x, a.y + wb.y);
            s[i1] = make_float2(a.x - wb.x, a.y - wb.y);
        }
        __syncthreads();
    }

    if (dir == 0) {
        for (int idx = tid; idx < 256 * 16; idx += 256) {
            int h = idx >> 4, kk = idx & 15;
            int k = k0 + kk;
            if (k < WF) {
                float2 v = S[kk * FPAD + h];
                size_t o = base + (size_t)h * WF + k;
                g_amp[o] = __fsqrt_rn(fmaf(v.x, v.x, v.y * v.y));
                g_pha[o] = atan2_acc(v.y, v.x);
            }
        }
    } else {
        for (int idx = tid; idx < 256 * 16; idx += 256) {
            int h = idx >> 4, kk = idx & 15;
            int k = k0 + kk;
            if (k < WF) g_XF[base + (size_t)h * WF + k] = S[kk * FPAD + h];
        }
    }
}

__global__ void ifft_row_kernel() {
    __shared__ float2 s[256];
    __shared__ float2 tw[128];
    int h = blockIdx.x & 255, bc = blockIdx.x >> 8, t = threadIdx.x;
    tw[t] = g_tw[t];
    size_t base = ((size_t)bc * 256 + h) * WF;
    s[t] = g_XF[base + t];
    float2 v;
    if (t == 0) v = g_XF[base + 128];
    else { float2 u = g_XF[base + 128 - t]; v = make_float2(u.x, -u.y); }
    s[t + 128] = v;
    __syncthreads();
    fft256_tab(s, tw, t, -1.f);   // inverse
    const float inv = 1.f / 65536.f;
    float* orow = g_xr + ((size_t)bc * 256 + h) * 256;
    orow[t]       = fabsf(s[t].x * inv);
    orow[t + 128] = fabsf(s[t + 128].x * inv);
}

// ---------------- 3x3 pad-1 conv 64->18 (packed f32x2, 9 acc pairs) ----------------
__global__ void conv_off_kernel(const float* __restrict__ wp, const float* __restrict__ bp, int srcflag) {
    __shared__ float T[18][19];
    __shared__ float wS[9][18];
    int w0b = blockIdx.x * 16, h0 = blockIdx.y * 16, b = blockIdx.z;
    const float* src = srcflag ? g_pha : g_amp;
    int tid = threadIdx.x;
    int tx = tid & 15, ty = tid >> 4;
    u64 acc[9];
#pragma unroll
    for (int j = 0; j < 9; j++) acc[j] = pack2(0.f, 0.f);

    for (int ic = 0; ic < CC; ic++) {
        __syncthreads();
        const float* P = src + (size_t)(b * CC + ic) * HWF;
        for (int idx = tid; idx < 18 * 18; idx += 256) {
            int r = idx / 18, cc = idx % 18;
            int gh = h0 + r - 1, gw = w0b + cc - 1;
            T[r][cc] = (gh >= 0 && gh < HH && gw >= 0 && gw < WF) ? P[gh * WF + gw] : 0.f;
        }
        if (tid < 162) {
            int k = tid / 18, o = tid % 18;
            wS[k][o] = wp[(o * CC + ic) * 9 + k];
        }
        __syncthreads();
#pragma unroll
        for (int k = 0; k < 9; k++) {
            float v = T[ty + k / 3][tx + k % 3];
            u64 V = pack2(v, v);
#pragma unroll
            for (int j = 0; j < 9; j++) {
                u64 Wv = *reinterpret_cast<const u64*>(&wS[k][2 * j]);
                fma2(acc[j], Wv, V);
            }
        }
    }
    int h = h0 + ty, w = w0b + tx;
    if (w < WF) {
#pragma unroll
        for (int j = 0; j < 9; j++) {
            float lo, hi; unpack2(acc[j], lo, hi);
            g_offs[((size_t)(b * 18 + 2 * j    ) * HH + h) * WF + w] = lo + bp[2 * j];
            g_offs[((size_t)(b * 18 + 2 * j + 1) * HH + h) * WF + w] = hi + bp[2 * j + 1];
        }
    }
}

// ---------------- sampling params ----------------
__device__ __forceinline__ int padidx(float qx, float qy) {
    int X = (int)qx, Y = (int)qy;
    if (X >= 1 && X <= 256 && Y >= 1 && Y <= 129) return (X - 1) * WF + (Y - 1);
    return -1;
}

__global__ void sample_params_kernel() {
    int idx = blockIdx.x * blockDim.x + threadIdx.x;
    if (idx >= BB * HWF * 9) return;
    int n = idx % 9;
    int rest = idx / 9;
    int w = rest % WF; rest /= WF;
    int h = rest % HH;
    int b = rest / HH;
    int i = n / 3, j = n % 3;
    float offx = g_offs[((size_t)(b * 18 + n) * HH + h) * WF + w];
    float offy = g_offs[((size_t)(b * 18 + n + 9) * HH + h) * WF + w];
    float px = (float)(h + 1) + (float)(i - 1) + offx;
    float py = (float)(w + 1) + (float)(j - 1) + offy;
    float qx = floorf(px), qy = floorf(py);
    const float HMax = 257.f, WMax = 130.f;
    float qltx = fminf(fmaxf(qx, 0.f), HMax);
    float qlty = fminf(fmaxf(qy, 0.f), WMax);
    float qrbx = fminf(fmaxf(qx + 1.f, 0.f), HMax);
    float qrby = fminf(fmaxf(qy + 1.f, 0.f), WMax);
    float cpx  = fminf(fmaxf(px, 0.f), HMax);
    float cpy  = fminf(fmaxf(py, 0.f), WMax);
    float glt = (1.f + (qltx - cpx)) * (1.f + (qlty - cpy));
    float grb = (1.f - (qrbx - cpx)) * (1.f - (qrby - cpy));
    float glb = (1.f + (qltx - cpx)) * (1.f - (qrby - cpy));
    float grt = (1.f - (qrbx - cpx)) * (1.f + (qlty - cpy));
    g_sidx[idx] = make_int4(padidx(qltx, qlty), padidx(qrbx, qrby),
                            padidx(qltx, qrby), padidx(qrbx, qlty));
    g_sw[idx] = make_float4(glt, grb, glb, grt);
}

// ---------------- gather ----------------
__global__ void gather_kernel(int srcflag) {
    size_t idx = (size_t)blockIdx.x * 256 + threadIdx.x;
    if (idx >= (size_t)NPIX) return;
    int w = (int)(idx % WF);
    size_t r = idx / WF;
    int h = (int)(r % HH); r /= HH;
    int c = (int)(r % CC);
    int b = (int)(r / CC);
    const float* P = (srcflag ? g_pha : g_amp) + (size_t)(b * CC + c) * HWF;
    float* Ep = g_E + (size_t)(b * CC + c) * EPLANE;
    size_t pb = (((size_t)b * HH + h) * WF + w) * 9;
#pragma unroll
    for (int n = 0; n < 9; n++) {
        int4 id = g_sidx[pb + n];
        float4 g = g_sw[pb + n];
        float v = 0.f;
        if (id.x >= 0) v += g.x * __ldg(P + id.x);
        if (id.y >= 0) v += g.y * __ldg(P + id.y);
        if (id.z >= 0) v += g.z * __ldg(P + id.z);
        if (id.w >= 0) v += g.w * __ldg(P + id.w);
        Ep[(size_t)(3 * h + n / 3) * W3 + (3 * w + n % 3)] = v;
    }
}

// ---------------- 3x3 stride-3 conv (16 oc packed as 8 pairs) ----------------
__global__ void conv_s3_kernel(const float* __restrict__ wc, int dstflag) {
    __shared__ float ES[48][49];
    __shared__ float wS[9][16];
    int ow0 = blockIdx.x * 16, oh0 = blockIdx.y * 16;
    int bz = blockIdx.z;
    int og = bz & 3;
    int b = bz >> 2;
    int tid = threadIdx.x;
    int tx = tid & 15, ty = tid >> 4;
    u64 acc[8];
#pragma unroll
    for (int j = 0; j < 8; j++) acc[j] = pack2(0.f, 0.f);
    int r_base = 3 * oh0 - 1, c_base = 3 * ow0 - 1;

    for (int ic = 0; ic < CC; ic++) {
        __syncthreads();
        const float* Ep = g_E + (size_t)(b * CC + ic) * EPLANE;
        for (int idx = tid; idx < 48 * 48; idx += 256) {
            int r = idx / 48, cc = idx % 48;
            int gr = r_base + r, gc = c_base + cc;
            ES[r][cc] = (gr >= 0 && gr < H3 && gc >= 0 && gc < W3)
                        ? Ep[(size_t)gr * W3 + gc] : 0.f;
        }
        if (tid < 144) {
            int k = tid / 16, o = tid % 16;
            wS[k][o] = wc[((og * 16 + o) * CC + ic) * 9 + k];
        }
        __syncthreads();
#pragma unroll
        for (int k = 0; k < 9; k++) {
            float v = ES[3 * ty + k / 3][3 * tx + k % 3];
            u64 V = pack2(v, v);
#pragma unroll
            for (int j = 0; j < 8; j++) {
                u64 Wv = *reinterpret_cast<const u64*>(&wS[k][2 * j]);
                fma2(acc[j], Wv, V);
            }
        }
    }
    int oh = oh0 + ty, ow = ow0 + tx;
    if (ow < WF) {
        float* dst = dstflag ? g_p3 : g_a3;
#pragma unroll
        for (int j = 0; j < 8; j++) {
            float lo, hi; unpack2(acc[j], lo, hi);
            int oc = og * 16 + 2 * j;
            dst[((size_t)(b * CC + oc    ) * HH + oh) * WF + ow] = lo;
            dst[((size_t)(b * CC + oc + 1) * HH + oh) * WF + ow] = hi;
        }
    }
}

// ---------------- 1x1 conv ----------------
__global__ void conv1x1_kernel(const float* __restrict__ w1, const float* __restrict__ b1,
                               int srcflag, int dstflag) {
    __shared__ float XS[64][33];
    __shared__ float WT[64][65];
    int p0 = blockIdx.x * 32;
    int b = blockIdx.y;
    int tid = threadIdx.x;
    const float* src = (srcflag ? g_pha : g_amp) + (size_t)b * CC * HWF;
    for (int idx = tid; idx < 2048; idx += 256) {
        int c = idx >> 5, p = idx & 31;
        XS[c][p] = src[(size_t)c * HWF + p0 + p];
    }
    for (int idx = tid; idx < 4096; idx += 256) {
        int oc = idx >> 6, k = idx & 63;
        WT[k][oc] = w1[idx];
    }
    __syncthreads();
    int px = tid & 31, ocg = tid >> 5;
    float acc[8] = {0.f, 0.f, 0.f, 0.f, 0.f, 0.f, 0.f, 0.f};
    for (int k = 0; k < 64; k++) {
        float xv = XS[k][px];
#pragma unroll
        for (int j = 0; j < 8; j++) acc[j] += WT[k][ocg + 8 * j] * xv;
    }
    float* dst = (dstflag ? g_p1 : g_a1) + (size_t)b * CC * HWF;
#pragma unroll
    for (int j = 0; j < 8; j++) {
        int oc = ocg + 8 * j;
        dst[(size_t)oc * HWF + p0 + px] = acc[j] + b1[oc];
    }
}

// ---------------- recombine ----------------
__global__ void combine_kernel() {
    size_t idx = (size_t)blockIdx.x * 256 + threadIdx.x;
    if (idx >= (size_t)NPIX) return;
    float a1 = g_a1[idx], p1 = g_p1[idx];
    float a3 = g_a3[idx], p3 = g_p3[idx];
    float s1, c1, s3, c3;
    sincos_acc(p1, &s1, &c1);
    sincos_acc(p3, &s3, &c3);
    g_XF[idx] = make_float2(a1 * c3 + a3 * c1 + 3e-8f,
                            a3 * s1 + a1 * s3 + 2e-8f);
}

// ---------------- final 5x5 conv (16 oc packed, 2 px/thread, 4-ic batch) ----------------
__global__ void conv5x5_kernel(const float* __restrict__ w0, const float* __restrict__ b0,
                               float* __restrict__ out) {
    __shared__ float T[4 * 36 * 21];
    __shared__ float wS[4][25][16];
    int w0b = blockIdx.x * 16, h0 = blockIdx.y * 32;
    int bz = blockIdx.z;
    int og = bz & 3;
    int b = bz >> 2;
    int tid = threadIdx.x;
    int tx = tid & 15, ty = tid >> 4;
    u64 acc0[8], acc1[8];
#pragma unroll
    for (int j = 0; j < 8; j++) { acc0[j] = pack2(0.f, 0.f); acc1[j] = pack2(0.f, 0.f); }

    for (int ic0 = 0; ic0 < CC; ic0 += 4) {
        __syncthreads();
        for (int idx = tid; idx < 4 * 756; idx += 256) {
            int ii = idx / 756;
            int rem = idx - ii * 756;
            int r = rem / 21, cc = rem - r * 21;
            int gh = h0 + r - 2, gw = w0b + cc - 2;
            const float* P = g_xr + (size_t)(b * CC + ic0 + ii) * HH * WW;
            T[idx] = (gh >= 0 && gh < HH && gw >= 0 && gw < WW && cc < 20)
                     ? P[(size_t)gh * WW + gw] : 0.f;
        }
        for (int idx = tid; idx < 1600; idx += 256) {
            int ii = idx / 400;
            int rem = idx - ii * 400;
            int k = rem / 16, o = rem - k * 16;
            wS[ii][k][o] = w0[((og * 16 + o) * CC + ic0 + ii) * 25 + k];
        }
        __syncthreads();
#pragma unroll
        for (int ii = 0; ii < 4; ii++) {
            const float* Tb = &T[ii * 756];
#pragma unroll
            for (int k = 0; k < 25; k++) {
                int ky = k / 5, kx = k % 5;
                float v0 = Tb[(2 * ty + ky) * 21 + tx + kx];
                float v1 = Tb[(2 * ty + 1 + ky) * 21 + tx + kx];
                u64 V0 = pack2(v0, v0);
                u64 V1 = pack2(v1, v1);
#pragma unroll
                for (int j = 0; j < 8; j++) {
                    u64 Wv = *reinterpret_cast<const u64*>(&wS[ii][k][2 * j]);
                    fma2(acc0[j], Wv, V0);
                    fma2(acc1[j], Wv, V1);
                }
            }
        }
    }
    int h = h0 + 2 * ty, w = w0b + tx;
#pragma unroll
    for (int j = 0; j < 8; j++) {
        int oc = og * 16 + 2 * j;
        float lo0, hi0, lo1, hi1;
        unpack2(acc0[j], lo0, hi0);
        unpack2(acc1[j], lo1, hi1);
        out[((size_t)(b * CC + oc    ) * HH + h) * WW + w]     = lo0 + b0[oc];
        out[((size_t)(b * CC + oc + 1) * HH + h) * WW + w]     = hi0 + b0[oc + 1];
        out[((size_t)(b * CC + oc    ) * HH + h + 1) * WW + w] = lo1 + b0[oc];
        out[((size_t)(b * CC + oc + 1) * HH + h + 1) * WW + w] = hi1 + b0[oc + 1];
    }
}

// ---------------- launcher ----------------
extern "C" void kernel_launch(void* const* d_in, const int* in_sizes, int n_in,
                              void* d_out, int out_size) {
    (void)in_sizes; (void)n_in; (void)out_size;
    const float* x    = (const float*)d_in[0];
    const float* wp_a = (const float*)d_in[1];
    const float* bp_a = (const float*)d_in[2];
    const float* wc_a = (const float*)d_in[3];
    const float* w1_a = (const float*)d_in[4];
    const float* b1_a = (const float*)d_in[5];
    const float* wp_p = (const float*)d_in[6];
    const float* bp_p = (const float*)d_in[7];
    const float* wc_p = (const float*)d_in[8];
    const float* w1_p = (const float*)d_in[9];
    const float* b1_p = (const float*)d_in[10];
    const float* w0   = (const float*)d_in[11];
    const float* b0   = (const float*)d_in[12];
    float* out = (float*)d_out;

    twiddle_init<<<1, 129>>>();

    fft_row_fwd<<<BB * CC * HH, 128>>>(x);
    fft_col_kernel<<<dim3(9, CC, BB), 256>>>(0);

    // amp branch
    conv_off_kernel<<<dim3(9, 16, BB), 256>>>(wp_a, bp_a, 0);
    sample_params_kernel<<<(BB * HWF * 9 + 255) / 256, 256>>>();
    gather_kernel<<<NPIX / 256, 256>>>(0);
    conv_s3_kernel<<<dim3(9, 16, BB * 4), 256>>>(wc_a, 0);
    conv1x1_kernel<<<dim3(HWF / 32, BB), 256>>>(w1_a, b1_a, 0, 0);

    // pha branch
    conv_off_kernel<<<dim3(9, 16, BB), 256>>>(wp_p, bp_p, 1);
    sample_params_kernel<<<(BB * HWF * 9 + 255) / 256, 256>>>();
    gather_kernel<<<NPIX / 256, 256>>>(1);
    conv_s3_kernel<<<dim3(9, 16, BB * 4), 256>>>(wc_p, 1);
    conv1x1_kernel<<<dim3(HWF / 32, BB), 256>>>(w1_p, b1_p, 1, 1);

    // recombine + inverse transform
    combine_kernel<<<NPIX / 256, 256>>>();
    fft_col_kernel<<<dim3(9, CC, BB), 256>>>(1);
    ifft_row_kernel<<<BB * CC * HH, 128>>>();

    conv5x5_kernel<<<dim3(16, 8, BB * 4), 256>>>(w0, b0, out);
}

// round 5
// speedup vs baseline: 1.4612x; 1.0437x over previous
#include <cuda_runtime.h>
#include <math.h>

#define BB 4
#define CC 64
#define HH 256
#define WW 256
#define WF 129
#define HWF (HH*WF)            // 33024
#define NPIX (BB*CC*HWF)       // 8454144
#define NP (BB*HWF)            // 132096
#define FPAD 261

// ---------------- scratch ----------------
__device__ float2 g_XF[NPIX];
__device__ float  g_amp[NPIX];
__device__ float  g_pha[NPIX];
__device__ float  g_a3[NPIX];
__device__ float  g_p3[NPIX];
__device__ float  g_a1[NPIX];
__device__ float  g_p1[NPIX];
__device__ float  g_offs[BB*18*HWF];
__device__ int4   g_sidx[9*NP];              // [n][b*h*w]
__device__ float4 g_sw[9*NP];                // [n][b*h*w]
__device__ float  g_S[(size_t)BB*CC*9*HWF];  // sample planes [b][c][n][h][w]
__device__ float  g_xr[(size_t)BB*CC*HH*WW];
__device__ float2 g_tw[129];

// ---------------- packed f32x2 helpers ----------------
typedef unsigned long long u64;
__device__ __forceinline__ u64 pack2(float lo, float hi) {
    u64 r; asm("mov.b64 %0, {%1, %2};" : "=l"(r) : "f"(lo), "f"(hi)); return r;
}
__device__ __forceinline__ void unpack2(u64 v, float& lo, float& hi) {
    asm("mov.b64 {%0, %1}, %2;" : "=f"(lo), "=f"(hi) : "l"(v));
}
__device__ __forceinline__ void fma2(u64& d, u64 a, u64 b) {
    asm("fma.rn.f32x2 %0, %1, %2, %0;" : "+l"(d) : "l"(a), "l"(b));
}

// ---------------- precise transcendentals ----------------
__device__ __forceinline__ void sincos_acc(float x, float* sp, float* cp) {
    float k = rintf(x * 0.63661977236758134f);
    float r = fmaf(k, -1.5707963705062866f, x);
    r = fmaf(k, 4.37113900018624e-8f, r);
    int q = (int)k;
    float z = r * r;
    float ss = 2.75573192e-6f;
    ss = fmaf(ss, z, -1.98412698e-4f);
    ss = fmaf(ss, z, 8.33333333e-3f);
    ss = fmaf(ss, z, -1.66666667e-1f);
    ss = fmaf(ss * z, r, r);
    float cc = -2.75573192e-7f;
    cc = fmaf(cc, z, 2.48015873e-5f);
    cc = fmaf(cc, z, -1.38888889e-3f);
    cc = fmaf(cc, z, 4.16666667e-2f);
    cc = fmaf(cc, z, -0.5f);
    cc = fmaf(cc, z, 1.0f);
    int qq = q & 3;
    float s_ = (qq & 1) ? cc : ss;
    float c_ = (qq & 1) ? ss : cc;
    if (qq == 1 || qq == 2) c_ = -c_;
    if (qq >= 2) s_ = -s_;
    *sp = s_; *cp = c_;
}

__device__ __forceinline__ float atan2_acc(float y, float x) {
    float ax = fabsf(x), ay = fabsf(y);
    float mx = fmaxf(ax, ay), mn = fminf(ax, ay);
    float t = (mx > 0.f) ? __fdiv_rn(mn, mx) : 0.f;
    float base = 0.f;
    if (t > 0.414213562f) { t = __fdiv_rn(t - 1.f, t + 1.f); base = 0.78539816339744831f; }
    float z = t * t;
    float p = -0.066666667f;
    p = fmaf(p, z,  0.076923077f);
    p = fmaf(p, z, -0.090909091f);
    p = fmaf(p, z,  0.111111111f);
    p = fmaf(p, z, -0.142857143f);
    p = fmaf(p, z,  0.2f);
    p = fmaf(p, z, -0.333333333f);
    float r = fmaf(t * z, p, t) + base;
    if (ay > ax) r = 1.57079632679489662f - r;
    if (x < 0.f) r = 3.14159265358979323f - r;
    return copysignf(r, y);
}

__global__ void twiddle_init() {
    int k = threadIdx.x;
    if (k < 129) {
        double a = -2.0 * 3.14159265358979323846 * (double)k / 256.0;
        float2 v = make_float2((float)cos(a), (float)sin(a));
        if (k == 0) v = make_float2(1.f, 0.f);
        g_tw[k] = v;
    }
}

// ---------------- FFT-256 (table = forward twiddles). sign=+1 fwd, -1 inv ----------------
__device__ __forceinline__ void fft256_tab(float2* s, const float2* tw, int t, float sign) {
#pragma unroll
    for (int kk = 0; kk < 2; kk++) {
        int i = t + (kk << 7);
        int j = __brev(i) >> 24;
        if (i < j) { float2 a = s[i]; s[i] = s[j]; s[j] = a; }
    }
    __syncthreads();
#pragma unroll
    for (int st = 1; st <= 8; st++) {
        int half = 1 << (st - 1);
        int g = t >> (st - 1);
        int p = t & (half - 1);
        int i0 = (g << st) + p;
        int i1 = i0 + half;
        float2 w = tw[p << (8 - st)];
        float wy = sign * w.y;
        float2 a = s[i0], b = s[i1];
        float2 wb = make_float2(w.x * b.x - wy * b.y, w.x * b.y + wy * b.x);
        s[i0] = make_float2(a.x + wb.x, a.y + wb.y);
        s[i1] = make_float2(a.x - wb.x, a.y - wb.y);
        __syncthreads();
    }
}

__global__ void fft_row_fwd(const float* __restrict__ x) {
    __shared__ float2 s[256];
    __shared__ float2 tw[128];
    int h = blockIdx.x & 255, bc = blockIdx.x >> 8, t = threadIdx.x;
    tw[t] = g_tw[t];
    const float* row = x + ((size_t)bc * 256 + h) * 256;
    s[t]       = make_float2(row[t], 0.f);
    s[t + 128] = make_float2(row[t + 128], 0.f);
    __syncthreads();
    fft256_tab(s, tw, t, +1.f);
    size_t ob = ((size_t)bc * 256 + h) * WF;
    g_XF[ob + t] = s[t];
    if (t == 0) g_XF[ob + 128] = s[128];
}

__global__ void fft_col_kernel(int dir) {
    __shared__ float2 S[16 * FPAD];
    __shared__ float2 tw[128];
    int k0 = blockIdx.x * 16;
    int c = blockIdx.y, b = blockIdx.z;
    int tid = threadIdx.x;
    if (tid < 128) tw[tid] = g_tw[tid];
    size_t base = ((size_t)(b * CC + c)) * HH * WF;

    for (int idx = tid; idx < 256 * 16; idx += 256) {
        int h = idx >> 4, kk = idx & 15;
        int k = k0 + kk;
        float2 v = (k < WF) ? g_XF[base + (size_t)h * WF + k] : make_float2(0.f, 0.f);
        S[kk * FPAD + h] = v;
    }
    __syncthreads();

    int f = tid >> 4;
    int l = tid & 15;
    float2* s = &S[f * FPAD];
#pragma unroll
    for (int m = 0; m < 16; m++) {
        int i = l + (m << 4);
        int j = __brev(i) >> 24;
        if (i < j) { float2 a = s[i]; s[i] = s[j]; s[j] = a; }
    }
    __syncthreads();
    float sign = dir ? -1.f : 1.f;
#pragma unroll
    for (int st = 1; st <= 8; st++) {
        int half = 1 << (st - 1);
#pragma unroll
        for (int m = 0; m < 8; m++) {
            int t = l + (m << 4);
            int g = t >> (st - 1);
            int p = t & (half - 1);
            int i0 = (g << st) + p;
            int i1 = i0 + half;
            float2 w = tw[p << (8 - st)];
            float wy = sign * w.y;
            float2 a = s[i0], bv = s[i1];
            float2 wb = make_float2(w.x * bv.x - wy * bv.y, w.x * bv.y + wy * bv.x);
            s[i0] = make_float2(a.x + wb.x, a.y + wb.y);
            s[i1] = make_float2(a.x - wb.x, a.y - wb.y);
        }
        __syncthreads();
    }

    if (dir == 0) {
        for (int idx = tid; idx < 256 * 16; idx += 256) {
            int h = idx >> 4, kk = idx & 15;
            int k = k0 + kk;
            if (k < WF) {
                float2 v = S[kk * FPAD + h];
                size_t o = base + (size_t)h * WF + k;
                g_amp[o] = __fsqrt_rn(fmaf(v.x, v.x, v.y * v.y));
                g_pha[o] = atan2_acc(v.y, v.x);
            }
        }
    } else {
        for (int idx = tid; idx < 256 * 16; idx += 256) {
            int h = idx >> 4, kk = idx & 15;
            int k = k0 + kk;
            if (k < WF) g_XF[base + (size_t)h * WF + k] = S[kk * FPAD + h];
        }
    }
}

__global__ void ifft_row_kernel() {
    __shared__ float2 s[256];
    __shared__ float2 tw[128];
    int h = blockIdx.x & 255, bc = blockIdx.x >> 8, t = threadIdx.x;
    tw[t] = g_tw[t];
    size_t base = ((size_t)bc * 256 + h) * WF;
    s[t] = g_XF[base + t];
    float2 v;
    if (t == 0) v = g_XF[base + 128];
    else { float2 u = g_XF[base + 128 - t]; v = make_float2(u.x, -u.y); }
    s[t + 128] = v;
    __syncthreads();
    fft256_tab(s, tw, t, -1.f);
    const float inv = 1.f / 65536.f;
    float* orow = g_xr + ((size_t)bc * 256 + h) * 256;
    orow[t]       = fabsf(s[t].x * inv);
    orow[t + 128] = fabsf(s[t + 128].x * inv);
}

// ---------------- 3x3 pad-1 conv 64->18, 2 px/thread (rows) ----------------
__global__ void conv_off_kernel(const float* __restrict__ wp, const float* __restrict__ bp, int srcflag) {
    __shared__ float T[34][18];
    __shared__ float wS[9][18];
    int w0b = blockIdx.x * 16, h0 = blockIdx.y * 32, b = blockIdx.z;
    const float* src = srcflag ? g_pha : g_amp;
    int tid = threadIdx.x;
    int tx = tid & 15, ty = tid >> 4;
    u64 acc0[9], acc1[9];
#pragma unroll
    for (int j = 0; j < 9; j++) { acc0[j] = pack2(0.f, 0.f); acc1[j] = pack2(0.f, 0.f); }

    for (int ic = 0; ic < CC; ic++) {
        __syncthreads();
        const float* P = src + (size_t)(b * CC + ic) * HWF;
        for (int idx = tid; idx < 34 * 18; idx += 256) {
            int r = idx / 18, cc = idx - r * 18;
            int gh = h0 + r - 1, gw = w0b + cc - 1;
            T[r][cc] = (gh >= 0 && gh < HH && gw >= 0 && gw < WF) ? P[gh * WF + gw] : 0.f;
        }
        if (tid < 162) {
            int k = tid / 18, o = tid % 18;
            wS[k][o] = wp[(o * CC + ic) * 9 + k];
        }
        __syncthreads();
#pragma unroll
        for (int k = 0; k < 9; k++) {
            int ky = k / 3, kx = k % 3;
            float v0 = T[2 * ty + ky][tx + kx];
            float v1 = T[2 * ty + 1 + ky][tx + kx];
            u64 V0 = pack2(v0, v0);
            u64 V1 = pack2(v1, v1);
#pragma unroll
            for (int j = 0; j < 9; j++) {
                u64 Wv = *reinterpret_cast<const u64*>(&wS[k][2 * j]);
                fma2(acc0[j], Wv, V0);
                fma2(acc1[j], Wv, V1);
            }
        }
    }
    int h = h0 + 2 * ty, w = w0b + tx;
    if (w < WF) {
#pragma unroll
        for (int j = 0; j < 9; j++) {
            float lo0, hi0, lo1, hi1;
            unpack2(acc0[j], lo0, hi0);
            unpack2(acc1[j], lo1, hi1);
            float blo = bp[2 * j], bhi = bp[2 * j + 1];
            g_offs[((size_t)(b * 18 + 2 * j    ) * HH + h) * WF + w]     = lo0 + blo;
            g_offs[((size_t)(b * 18 + 2 * j + 1) * HH + h) * WF + w]     = hi0 + bhi;
            g_offs[((size_t)(b * 18 + 2 * j    ) * HH + h + 1) * WF + w] = lo1 + blo;
            g_offs[((size_t)(b * 18 + 2 * j + 1) * HH + h + 1) * WF + w] = hi1 + bhi;
        }
    }
}

// ---------------- sampling params (n-major layout) ----------------
__device__ __forceinline__ int padidx(float qx, float qy) {
    int X = (int)qx, Y = (int)qy;
    if (X >= 1 && X <= 256 && Y >= 1 && Y <= 129) return (X - 1) * WF + (Y - 1);
    return -1;
}

__global__ void sample_params_kernel() {
    int idx = blockIdx.x * blockDim.x + threadIdx.x;
    if (idx >= NP * 9) return;
    int n = idx % 9;
    int pix = idx / 9;
    int w = pix % WF;
    int rest = pix / WF;
    int h = rest % HH;
    int b = rest / HH;
    int i = n / 3, j = n % 3;
    float offx = g_offs[((size_t)(b * 18 + n) * HH + h) * WF + w];
    float offy = g_offs[((size_t)(b * 18 + n + 9) * HH + h) * WF + w];
    float px = (float)(h + 1) + (float)(i - 1) + offx;
    float py = (float)(w + 1) + (float)(j - 1) + offy;
    float qx = floorf(px), qy = floorf(py);
    const float HMax = 257.f, WMax = 130.f;
    float qltx = fminf(fmaxf(qx, 0.f), HMax);
    float qlty = fminf(fmaxf(qy, 0.f), WMax);
    float qrbx = fminf(fmaxf(qx + 1.f, 0.f), HMax);
    float qrby = fminf(fmaxf(qy + 1.f, 0.f), WMax);
    float cpx  = fminf(fmaxf(px, 0.f), HMax);
    float cpy  = fminf(fmaxf(py, 0.f), WMax);
    float glt = (1.f + (qltx - cpx)) * (1.f + (qlty - cpy));
    float grb = (1.f - (qrbx - cpx)) * (1.f - (qrby - cpy));
    float glb = (1.f + (qltx - cpx)) * (1.f - (qrby - cpy));
    float grt = (1.f - (qrbx - cpx)) * (1.f + (qlty - cpy));
    g_sidx[n * NP + pix] = make_int4(padidx(qltx, qlty), padidx(qrbx, qrby),
                                     padidx(qltx, qrby), padidx(qrbx, qlty));
    g_sw[n * NP + pix] = make_float4(glt, grb, glb, grt);
}

// ---------------- gather: 8 channels/thread, plane-layout coalesced stores ----------------
__global__ void gather_kernel(int srcflag) {
    int t = blockIdx.x * 256 + threadIdx.x;
    if (t >= NP * 8) return;
    int w = t % WF;
    int r = t / WF;
    int h = r % HH; r /= HH;
    int cg = r & 7;
    int b = r >> 3;
    int pix = (b * HH + h) * WF + w;

    int4   id[9];
    float4 gw[9];
#pragma unroll
    for (int n = 0; n < 9; n++) {
        id[n] = g_sidx[n * NP + pix];
        gw[n] = g_sw[n * NP + pix];
    }
    const float* srcb = (srcflag ? g_pha : g_amp);
#pragma unroll
    for (int cc = 0; cc < 8; cc++) {
        int c = cg * 8 + cc;
        const float* P = srcb + (size_t)(b * CC + c) * HWF;
        float* Sp = g_S + ((size_t)(b * CC + c) * 9) * HWF + (size_t)h * WF + w;
#pragma unroll
        for (int n = 0; n < 9; n++) {
            float v = 0.f;
            if (id[n].x >= 0) v += gw[n].x * __ldg(P + id[n].x);
            if (id[n].y >= 0) v += gw[n].y * __ldg(P + id[n].y);
            if (id[n].z >= 0) v += gw[n].z * __ldg(P + id[n].z);
            if (id[n].w >= 0) v += gw[n].w * __ldg(P + id[n].w);
            Sp[(size_t)n * HWF] = v;
        }
    }
}

// ---------------- deform conv: 9 sample planes, 32 oc/block, 2 px/thread ----------------
__global__ void conv_s3_kernel(const float* __restrict__ wc, int dstflag) {
    __shared__ float SS[9][33][18];
    __shared__ float wS[9][32];
    int w0 = blockIdx.x * 16, h0 = blockIdx.y * 32;
    int bz = blockIdx.z;
    int og = bz & 1;
    int b = bz >> 1;
    int tid = threadIdx.x;
    int tx = tid & 15, ty = tid >> 4;
    u64 acc0[16], acc1[16];
#pragma unroll
    for (int j = 0; j < 16; j++) { acc0[j] = pack2(0.f, 0.f); acc1[j] = pack2(0.f, 0.f); }

    const int ni[3] = {2, 0, 1};
    const int dd[3] = {-1, 0, 0};

    for (int ic = 0; ic < CC; ic++) {
        __syncthreads();
        const float* Sb = g_S + ((size_t)(b * CC + ic) * 9) * HWF;
        for (int idx = tid; idx < 9 * 33 * 18; idx += 256) {
            int n = idx / 594;
            int rem = idx - n * 594;
            int rr = rem / 18, cc = rem - rr * 18;
            int gh = h0 - 1 + rr, gw = w0 - 1 + cc;
            SS[n][rr][cc] = (gh >= 0 && gh < HH && gw >= 0 && gw < WF)
                            ? Sb[(size_t)n * HWF + gh * WF + gw] : 0.f;
        }
        // 288 weight loads with a 256-thread block: strided loop (R4 bug fix)
        for (int idx = tid; idx < 9 * 32; idx += 256) {
            int k = idx >> 5, o = idx & 31;
            wS[k][o] = wc[((og * 32 + o) * CC + ic) * 9 + k];
        }
        __syncthreads();
#pragma unroll
        for (int rr = 0; rr < 3; rr++) {
#pragma unroll
            for (int c3 = 0; c3 < 3; c3++) {
                int n = ni[rr] * 3 + ni[c3];
                int row = 2 * ty + 1 + dd[rr];
                int col = tx + 1 + dd[c3];
                float v0 = SS[n][row][col];
                float v1 = SS[n][row + 1][col];
                u64 V0 = pack2(v0, v0);
                u64 V1 = pack2(v1, v1);
                int k = rr * 3 + c3;
#pragma unroll
                for (int j = 0; j < 16; j++) {
                    u64 Wv = *reinterpret_cast<const u64*>(&wS[k][2 * j]);
                    fma2(acc0[j], Wv, V0);
                    fma2(acc1[j], Wv, V1);
                }
            }
        }
    }
    int oh = h0 + 2 * ty, ow = w0 + tx;
    if (ow < WF) {
        float* dst = dstflag ? g_p3 : g_a3;
#pragma unroll
        for (int j = 0; j < 16; j++) {
            float lo0, hi0, lo1, hi1;
            unpack2(acc0[j], lo0, hi0);
            unpack2(acc1[j], lo1, hi1);
            int oc = og * 32 + 2 * j;
            dst[((size_t)(b * CC + oc    ) * HH + oh) * WF + ow]     = lo0;
            dst[((size_t)(b * CC + oc + 1) * HH + oh) * WF + ow]     = hi0;
            dst[((size_t)(b * CC + oc    ) * HH + oh + 1) * WF + ow] = lo1;
            dst[((size_t)(b * CC + oc + 1) * HH + oh + 1) * WF + ow] = hi1;
        }
    }
}

// ---------------- 1x1 conv ----------------
__global__ void conv1x1_kernel(const float* __restrict__ w1, const float* __restrict__ b1,
                               int srcflag, int dstflag) {
    __shared__ float XS[64][33];
    __shared__ float WT[64][65];
    int p0 = blockIdx.x * 32;
    int b = blockIdx.y;
    int tid = threadIdx.x;
    const float* src = (srcflag ? g_pha : g_amp) + (size_t)b * CC * HWF;
    for (int idx = tid; idx < 2048; idx += 256) {
        int c = idx >> 5, p = idx & 31;
        XS[c][p] = src[(size_t)c * HWF + p0 + p];
    }
    for (int idx = tid; idx < 4096; idx += 256) {
        int oc = idx >> 6, k = idx & 63;
        WT[k][oc] = w1[idx];
    }
    __syncthreads();
    int px = tid & 31, ocg = tid >> 5;
    float acc[8] = {0.f, 0.f, 0.f, 0.f, 0.f, 0.f, 0.f, 0.f};
    for (int k = 0; k < 64; k++) {
        float xv = XS[k][px];
#pragma unroll
        for (int j = 0; j < 8; j++) acc[j] += WT[k][ocg + 8 * j] * xv;
    }
    float* dst = (dstflag ? g_p1 : g_a1) + (size_t)b * CC * HWF;
#pragma unroll
    for (int j = 0; j < 8; j++) {
        int oc = ocg + 8 * j;
        dst[(size_t)oc * HWF + p0 + px] = acc[j] + b1[oc];
    }
}

// ---------------- recombine ----------------
__global__ void combine_kernel() {
    size_t idx = (size_t)blockIdx.x * 256 + threadIdx.x;
    if (idx >= (size_t)NPIX) return;
    float a1 = g_a1[idx], p1 = g_p1[idx];
    float a3 = g_a3[idx], p3 = g_p3[idx];
    float s1, c1, s3, c3;
    sincos_acc(p1, &s1, &c1);
    sincos_acc(p3, &s3, &c3);
    g_XF[idx] = make_float2(a1 * c3 + a3 * c1 + 3e-8f,
                            a3 * s1 + a1 * s3 + 2e-8f);
}

// ---------------- final 5x5 conv: 16 oc packed, 2x2 px/thread, 4-ic batch ----------------
__global__ void conv5x5_kernel(const float* __restrict__ w0, const float* __restrict__ b0,
                               float* __restrict__ out) {
    __shared__ float T[4 * 36 * 37];
    __shared__ float wS[4][25][16];
    int w0b = blockIdx.x * 32, h0 = blockIdx.y * 32;
    int bz = blockIdx.z;
    int og = bz & 3;
    int b = bz >> 2;
    int tid = threadIdx.x;
    int tx = tid & 15, ty = tid >> 4;
    u64 acc00[8], acc01[8], acc10[8], acc11[8];
#pragma unroll
    for (int j = 0; j < 8; j++) {
        acc00[j] = pack2(0.f, 0.f); acc01[j] = pack2(0.f, 0.f);
        acc10[j] = pack2(0.f, 0.f); acc11[j] = pack2(0.f, 0.f);
    }

    for (int ic0 = 0; ic0 < CC; ic0 += 4) {
        __syncthreads();
        for (int idx = tid; idx < 4 * 1296; idx += 256) {
            int ii = idx / 1296;
            int rem = idx - ii * 1296;
            int r = rem / 36, cc = rem - r * 36;
            int gh = h0 + r - 2, gw = w0b + cc - 2;
            const float* P = g_xr + (size_t)(b * CC + ic0 + ii) * HH * WW;
            T[ii * 1332 + r * 37 + cc] = (gh >= 0 && gh < HH && gw >= 0 && gw < WW)
                                         ? P[(size_t)gh * WW + gw] : 0.f;
        }
        for (int idx = tid; idx < 1600; idx += 256) {
            int ii = idx / 400;
            int rem = idx - ii * 400;
            int k = rem / 16, o = rem - k * 16;
            wS[ii][k][o] = w0[((og * 16 + o) * CC + ic0 + ii) * 25 + k];
        }
        __syncthreads();
#pragma unroll
        for (int ii = 0; ii < 4; ii++) {
            const float* Tb = &T[ii * 1332];
#pragma unroll
            for (int k = 0; k < 25; k++) {
                int ky = k / 5, kx = k % 5;
                const float* row0 = Tb + (2 * ty + ky) * 37 + 2 * tx + kx;
                float v00 = row0[0];
                float v01 = row0[1];
                float v10 = row0[37];
                float v11 = row0[38];
                u64 V00 = pack2(v00, v00);
                u64 V01 = pack2(v01, v01);
                u64 V10 = pack2(v10, v10);
                u64 V11 = pack2(v11, v11);
#pragma unroll
                for (int j = 0; j < 8; j++) {
                    u64 Wv = *reinterpret_cast<const u64*>(&wS[ii][k][2 * j]);
                    fma2(acc00[j], Wv, V00);
                    fma2(acc01[j], Wv, V01);
                    fma2(acc10[j], Wv, V10);
                    fma2(acc11[j], Wv, V11);
                }
            }
        }
    }
    int h = h0 + 2 * ty, w = w0b + 2 * tx;
#pragma unroll
    for (int j = 0; j < 8; j++) {
        int oc = og * 16 + 2 * j;
        float l00, h00, l01, h01, l10, h10, l11, h11;
        unpack2(acc00[j], l00, h00);
        unpack2(acc01[j], l01, h01);
        unpack2(acc10[j], l10, h10);
        unpack2(acc11[j], l11, h11);
        float blo = b0[oc], bhi = b0[oc + 1];
        float* o0 = out + ((size_t)(b * CC + oc) * HH + h) * WW + w;
        float* o1 = out + ((size_t)(b * CC + oc + 1) * HH + h) * WW + w;
        o0[0] = l00 + blo;  o0[1] = l01 + blo;
        o0[WW] = l10 + blo; o0[WW + 1] = l11 + blo;
        o1[0] = h00 + bhi;  o1[1] = h01 + bhi;
        o1[WW] = h10 + bhi; o1[WW + 1] = h11 + bhi;
    }
}

// ---------------- launcher ----------------
extern "C" void kernel_launch(void* const* d_in, const int* in_sizes, int n_in,
                              void* d_out, int out_size) {
    (void)in_sizes; (void)n_in; (void)out_size;
    const float* x    = (const float*)d_in[0];
    const float* wp_a = (const float*)d_in[1];
    const float* bp_a = (const float*)d_in[2];
    const float* wc_a = (const float*)d_in[3];
    const float* w1_a = (const float*)d_in[4];
    const float* b1_a = (const float*)d_in[5];
    const float* wp_p = (const float*)d_in[6];
    const float* bp_p = (const float*)d_in[7];
    const float* wc_p = (const float*)d_in[8];
    const float* w1_p = (const float*)d_in[9];
    const float* b1_p = (const float*)d_in[10];
    const float* w0   = (const float*)d_in[11];
    const float* b0   = (const float*)d_in[12];
    float* out = (float*)d_out;

    twiddle_init<<<1, 129>>>();

    fft_row_fwd<<<BB * CC * HH, 128>>>(x);
    fft_col_kernel<<<dim3(9, CC, BB), 256>>>(0);

    // amp branch
    conv_off_kernel<<<dim3(9, 8, BB), 256>>>(wp_a, bp_a, 0);
    sample_params_kernel<<<(NP * 9 + 255) / 256, 256>>>();
    gather_kernel<<<(NP * 8 + 255) / 256, 256>>>(0);
    conv_s3_kernel<<<dim3(9, 8, BB * 2), 256>>>(wc_a, 0);
    conv1x1_kernel<<<dim3(HWF / 32, BB), 256>>>(w1_a, b1_a, 0, 0);

    // pha branch
    conv_off_kernel<<<dim3(9, 8, BB), 256>>>(wp_p, bp_p, 1);
    sample_params_kernel<<<(NP * 9 + 255) / 256, 256>>>();
    gather_kernel<<<(NP * 8 + 255) / 256, 256>>>(1);
    conv_s3_kernel<<<dim3(9, 8, BB * 2), 256>>>(wc_p, 1);
    conv1x1_kernel<<<dim3(HWF / 32, BB), 256>>>(w1_p, b1_p, 1, 1);

    // recombine + inverse transform
    combine_kernel<<<NPIX / 256, 256>>>();
    fft_col_kernel<<<dim3(9, CC, BB), 256>>>(1);
    ifft_row_kernel<<<BB * CC * HH, 128>>>();

    conv5x5_kernel<<<dim3(8, 8, BB * 4), 256>>>(w0, b0, out);
}

// round 6
// speedup vs baseline: 1.5160x; 1.0375x over previous
#include <cuda_runtime.h>
#include <math.h>

#define BB 4
#define CC 64
#define HH 256
#define WW 256
#define WF 129
#define HWF (HH*WF)            // 33024
#define NPIX (BB*CC*HWF)       // 8454144
#define NP (BB*HWF)            // 132096
#define FPAD 261

// ---------------- scratch (branch axis f: 0=amp, 1=pha) ----------------
__device__ float2 g_XF[NPIX];
__device__ float  g_amp[NPIX];
__device__ float  g_pha[NPIX];
__device__ float  g_a3[NPIX];
__device__ float  g_p3[NPIX];
__device__ float  g_a1[NPIX];
__device__ float  g_p1[NPIX];
__device__ float  g_offs[2*BB*18*HWF];
__device__ int4   g_sidx[2*9*NP];
__device__ float4 g_sw[2*9*NP];
__device__ float  g_S[(size_t)2*BB*CC*9*HWF];   // sample planes [f][b][c][n][h][w]
__device__ float  g_xr[(size_t)BB*CC*HH*WW];
__device__ float2 g_tw[129];

#define SBR ((size_t)BB*CC*9*HWF)   // per-branch g_S stride

// ---------------- packed f32x2 helpers ----------------
typedef unsigned long long u64;
__device__ __forceinline__ u64 pack2(float lo, float hi) {
    u64 r; asm("mov.b64 %0, {%1, %2};" : "=l"(r) : "f"(lo), "f"(hi)); return r;
}
__device__ __forceinline__ void unpack2(u64 v, float& lo, float& hi) {
    asm("mov.b64 {%0, %1}, %2;" : "=f"(lo), "=f"(hi) : "l"(v));
}
__device__ __forceinline__ void fma2(u64& d, u64 a, u64 b) {
    asm("fma.rn.f32x2 %0, %1, %2, %0;" : "+l"(d) : "l"(a), "l"(b));
}

// ---------------- precise transcendentals ----------------
__device__ __forceinline__ void sincos_acc(float x, float* sp, float* cp) {
    float k = rintf(x * 0.63661977236758134f);
    float r = fmaf(k, -1.5707963705062866f, x);
    r = fmaf(k, 4.37113900018624e-8f, r);
    int q = (int)k;
    float z = r * r;
    float ss = 2.75573192e-6f;
    ss = fmaf(ss, z, -1.98412698e-4f);
    ss = fmaf(ss, z, 8.33333333e-3f);
    ss = fmaf(ss, z, -1.66666667e-1f);
    ss = fmaf(ss * z, r, r);
    float cc = -2.75573192e-7f;
    cc = fmaf(cc, z, 2.48015873e-5f);
    cc = fmaf(cc, z, -1.38888889e-3f);
    cc = fmaf(cc, z, 4.16666667e-2f);
    cc = fmaf(cc, z, -0.5f);
    cc = fmaf(cc, z, 1.0f);
    int qq = q & 3;
    float s_ = (qq & 1) ? cc : ss;
    float c_ = (qq & 1) ? ss : cc;
    if (qq == 1 || qq == 2) c_ = -c_;
    if (qq >= 2) s_ = -s_;
    *sp = s_; *cp = c_;
}

__device__ __forceinline__ float atan2_acc(float y, float x) {
    float ax = fabsf(x), ay = fabsf(y);
    float mx = fmaxf(ax, ay), mn = fminf(ax, ay);
    float t = (mx > 0.f) ? __fdiv_rn(mn, mx) : 0.f;
    float base = 0.f;
    if (t > 0.414213562f) { t = __fdiv_rn(t - 1.f, t + 1.f); base = 0.78539816339744831f; }
    float z = t * t;
    float p = -0.066666667f;
    p = fmaf(p, z,  0.076923077f);
    p = fmaf(p, z, -0.090909091f);
    p = fmaf(p, z,  0.111111111f);
    p = fmaf(p, z, -0.142857143f);
    p = fmaf(p, z,  0.2f);
    p = fmaf(p, z, -0.333333333f);
    float r = fmaf(t * z, p, t) + base;
    if (ay > ax) r = 1.57079632679489662f - r;
    if (x < 0.f) r = 3.14159265358979323f - r;
    return copysignf(r, y);
}

__global__ void twiddle_init() {
    int k = threadIdx.x;
    if (k < 129) {
        double a = -2.0 * 3.14159265358979323846 * (double)k / 256.0;
        float2 v = make_float2((float)cos(a), (float)sin(a));
        if (k == 0) v = make_float2(1.f, 0.f);
        g_tw[k] = v;
    }
}

// ---------------- FFT-256 (table = forward twiddles). sign=+1 fwd, -1 inv ----------------
__device__ __forceinline__ void fft256_tab(float2* s, const float2* tw, int t, float sign) {
#pragma unroll
    for (int kk = 0; kk < 2; kk++) {
        int i = t + (kk << 7);
        int j = __brev(i) >> 24;
        if (i < j) { float2 a = s[i]; s[i] = s[j]; s[j] = a; }
    }
    __syncthreads();
#pragma unroll
    for (int st = 1; st <= 8; st++) {
        int half = 1 << (st - 1);
        int g = t >> (st - 1);
        int p = t & (half - 1);
        int i0 = (g << st) + p;
        int i1 = i0 + half;
        float2 w = tw[p << (8 - st)];
        float wy = sign * w.y;
        float2 a = s[i0], b = s[i1];
        float2 wb = make_float2(w.x * b.x - wy * b.y, w.x * b.y + wy * b.x);
        s[i0] = make_float2(a.x + wb.x, a.y + wb.y);
        s[i1] = make_float2(a.x - wb.x, a.y - wb.y);
        __syncthreads();
    }
}

__global__ void fft_row_fwd(const float* __restrict__ x) {
    __shared__ float2 s[256];
    __shared__ float2 tw[128];
    int h = blockIdx.x & 255, bc = blockIdx.x >> 8, t = threadIdx.x;
    tw[t] = g_tw[t];
    const float* row = x + ((size_t)bc * 256 + h) * 256;
    s[t]       = make_float2(row[t], 0.f);
    s[t + 128] = make_float2(row[t + 128], 0.f);
    __syncthreads();
    fft256_tab(s, tw, t, +1.f);
    size_t ob = ((size_t)bc * 256 + h) * WF;
    g_XF[ob + t] = s[t];
    if (t == 0) g_XF[ob + 128] = s[128];
}

__global__ void fft_col_kernel(int dir) {
    __shared__ float2 S[16 * FPAD];
    __shared__ float2 tw[128];
    int k0 = blockIdx.x * 16;
    int c = blockIdx.y, b = blockIdx.z;
    int tid = threadIdx.x;
    if (tid < 128) tw[tid] = g_tw[tid];
    size_t base = ((size_t)(b * CC + c)) * HH * WF;

    for (int idx = tid; idx < 256 * 16; idx += 256) {
        int h = idx >> 4, kk = idx & 15;
        int k = k0 + kk;
        float2 v = (k < WF) ? g_XF[base + (size_t)h * WF + k] : make_float2(0.f, 0.f);
        S[kk * FPAD + h] = v;
    }
    __syncthreads();

    int f = tid >> 4;
    int l = tid & 15;
    float2* s = &S[f * FPAD];
#pragma unroll
    for (int m = 0; m < 16; m++) {
        int i = l + (m << 4);
        int j = __brev(i) >> 24;
        if (i < j) { float2 a = s[i]; s[i] = s[j]; s[j] = a; }
    }
    __syncthreads();
    float sign = dir ? -1.f : 1.f;
#pragma unroll
    for (int st = 1; st <= 8; st++) {
        int half = 1 << (st - 1);
#pragma unroll
        for (int m = 0; m < 8; m++) {
            int t = l + (m << 4);
            int g = t >> (st - 1);
            int p = t & (half - 1);
            int i0 = (g << st) + p;
            int i1 = i0 + half;
            float2 w = tw[p << (8 - st)];
            float wy = sign * w.y;
            float2 a = s[i0], bv = s[i1];
            float2 wb = make_float2(w.x * bv.x - wy * bv.y, w.x * bv.y + wy * bv.x);
            s[i0] = make_float2(a.x + wb.x, a.y + wb.y);
            s[i1] = make_float2(a.x - wb.x, a.y - wb.y);
        }
        __syncthreads();
    }

    if (dir == 0) {
        for (int idx = tid; idx < 256 * 16; idx += 256) {
            int h = idx >> 4, kk = idx & 15;
            int k = k0 + kk;
            if (k < WF) {
                float2 v = S[kk * FPAD + h];
                size_t o = base + (size_t)h * WF + k;
                g_amp[o] = __fsqrt_rn(fmaf(v.x, v.x, v.y * v.y));
                g_pha[o] = atan2_acc(v.y, v.x);
            }
        }
    } else {
        for (int idx = tid; idx < 256 * 16; idx += 256) {
            int h = idx >> 4, kk = idx & 15;
            int k = k0 + kk;
            if (k < WF) g_XF[base + (size_t)h * WF + k] = S[kk * FPAD + h];
        }
    }
}

__global__ void ifft_row_kernel() {
    __shared__ float2 s[256];
    __shared__ float2 tw[128];
    int h = blockIdx.x & 255, bc = blockIdx.x >> 8, t = threadIdx.x;
    tw[t] = g_tw[t];
    size_t base = ((size_t)bc * 256 + h) * WF;
    s[t] = g_XF[base + t];
    float2 v;
    if (t == 0) v = g_XF[base + 128];
    else { float2 u = g_XF[base + 128 - t]; v = make_float2(u.x, -u.y); }
    s[t + 128] = v;
    __syncthreads();
    fft256_tab(s, tw, t, -1.f);
    const float inv = 1.f / 65536.f;
    float* orow = g_xr + ((size_t)bc * 256 + h) * 256;
    orow[t]       = fabsf(s[t].x * inv);
    orow[t + 128] = fabsf(s[t + 128].x * inv);
}

// ---------------- merged 3x3 pad-1 conv 64->18, both branches ----------------
__global__ void __launch_bounds__(256, 3)
conv_off_kernel(const float* __restrict__ wp_a, const float* __restrict__ bp_a,
                const float* __restrict__ wp_p, const float* __restrict__ bp_p) {
    __shared__ float T[34][18];
    __shared__ float wS[9][18];
    int w0b = blockIdx.x * 16, h0 = blockIdx.y * 32;
    int bz = blockIdx.z;
    int f = bz & 1, b = bz >> 1;
    const float* src = f ? g_pha : g_amp;
    const float* wp = f ? wp_p : wp_a;
    const float* bp = f ? bp_p : bp_a;
    int tid = threadIdx.x;
    int tx = tid & 15, ty = tid >> 4;
    u64 acc0[9], acc1[9];
#pragma unroll
    for (int j = 0; j < 9; j++) { acc0[j] = pack2(0.f, 0.f); acc1[j] = pack2(0.f, 0.f); }

    for (int ic = 0; ic < CC; ic++) {
        __syncthreads();
        const float* P = src + (size_t)(b * CC + ic) * HWF;
        for (int idx = tid; idx < 34 * 18; idx += 256) {
            int r = idx / 18, cc = idx - r * 18;
            int gh = h0 + r - 1, gw = w0b + cc - 1;
            T[r][cc] = (gh >= 0 && gh < HH && gw >= 0 && gw < WF) ? P[gh * WF + gw] : 0.f;
        }
        if (tid < 162) {
            int k = tid / 18, o = tid % 18;
            wS[k][o] = wp[(o * CC + ic) * 9 + k];
        }
        __syncthreads();
#pragma unroll
        for (int k = 0; k < 9; k++) {
            int ky = k / 3, kx = k % 3;
            float v0 = T[2 * ty + ky][tx + kx];
            float v1 = T[2 * ty + 1 + ky][tx + kx];
            u64 V0 = pack2(v0, v0);
            u64 V1 = pack2(v1, v1);
#pragma unroll
            for (int j = 0; j < 9; j++) {
                u64 Wv = *reinterpret_cast<const u64*>(&wS[k][2 * j]);
                fma2(acc0[j], Wv, V0);
                fma2(acc1[j], Wv, V1);
            }
        }
    }
    int h = h0 + 2 * ty, w = w0b + tx;
    if (w < WF) {
#pragma unroll
        for (int j = 0; j < 9; j++) {
            float lo0, hi0, lo1, hi1;
            unpack2(acc0[j], lo0, hi0);
            unpack2(acc1[j], lo1, hi1);
            float blo = bp[2 * j], bhi = bp[2 * j + 1];
            size_t base = (size_t)((f * BB + b) * 18);
            g_offs[((base + 2 * j    ) * HH + h) * WF + w]     = lo0 + blo;
            g_offs[((base + 2 * j + 1) * HH + h) * WF + w]     = hi0 + bhi;
            g_offs[((base + 2 * j    ) * HH + h + 1) * WF + w] = lo1 + blo;
            g_offs[((base + 2 * j + 1) * HH + h + 1) * WF + w] = hi1 + bhi;
        }
    }
}

// ---------------- sampling params (merged, n-major layout) ----------------
__device__ __forceinline__ int padidx(float qx, float qy) {
    int X = (int)qx, Y = (int)qy;
    if (X >= 1 && X <= 256 && Y >= 1 && Y <= 129) return (X - 1) * WF + (Y - 1);
    return -1;
}

__global__ void sample_params_kernel() {
    int idx = blockIdx.x * blockDim.x + threadIdx.x;
    if (idx >= NP * 9) return;
    int f = blockIdx.y;
    int n = idx % 9;
    int pix = idx / 9;
    int w = pix % WF;
    int rest = pix / WF;
    int h = rest % HH;
    int b = rest / HH;
    int i = n / 3, j = n % 3;
    size_t obase = (size_t)((f * BB + b) * 18);
    float offx = g_offs[((obase + n    ) * HH + h) * WF + w];
    float offy = g_offs[((obase + n + 9) * HH + h) * WF + w];
    float px = (float)(h + 1) + (float)(i - 1) + offx;
    float py = (float)(w + 1) + (float)(j - 1) + offy;
    float qx = floorf(px), qy = floorf(py);
    const float HMax = 257.f, WMax = 130.f;
    float qltx = fminf(fmaxf(qx, 0.f), HMax);
    float qlty = fminf(fmaxf(qy, 0.f), WMax);
    float qrbx = fminf(fmaxf(qx + 1.f, 0.f), HMax);
    float qrby = fminf(fmaxf(qy + 1.f, 0.f), WMax);
    float cpx  = fminf(fmaxf(px, 0.f), HMax);
    float cpy  = fminf(fmaxf(py, 0.f), WMax);
    float glt = (1.f + (qltx - cpx)) * (1.f + (qlty - cpy));
    float grb = (1.f - (qrbx - cpx)) * (1.f - (qrby - cpy));
    float glb = (1.f + (qltx - cpx)) * (1.f - (qrby - cpy));
    float grt = (1.f - (qrbx - cpx)) * (1.f + (qlty - cpy));
    g_sidx[f * 9 * NP + n * NP + pix] = make_int4(padidx(qltx, qlty), padidx(qrbx, qrby),
                                                  padidx(qltx, qrby), padidx(qrbx, qlty));
    g_sw[f * 9 * NP + n * NP + pix] = make_float4(glt, grb, glb, grt);
}

// ---------------- gather (merged): 8 channels/thread ----------------
__global__ void gather_kernel() {
    int t = blockIdx.x * 256 + threadIdx.x;
    if (t >= NP * 8) return;
    int f = blockIdx.y;
    int w = t % WF;
    int r = t / WF;
    int h = r % HH; r /= HH;
    int cg = r & 7;
    int b = r >> 3;
    int pix = (b * HH + h) * WF + w;

    int4   id[9];
    float4 gw[9];
#pragma unroll
    for (int n = 0; n < 9; n++) {
        id[n] = g_sidx[f * 9 * NP + n * NP + pix];
        gw[n] = g_sw[f * 9 * NP + n * NP + pix];
    }
    const float* srcb = (f ? g_pha : g_amp);
    float* Sbr = g_S + (size_t)f * SBR;
#pragma unroll
    for (int cc = 0; cc < 8; cc++) {
        int c = cg * 8 + cc;
        const float* P = srcb + (size_t)(b * CC + c) * HWF;
        float* Sp = Sbr + ((size_t)(b * CC + c) * 9) * HWF + (size_t)h * WF + w;
#pragma unroll
        for (int n = 0; n < 9; n++) {
            float v = 0.f;
            if (id[n].x >= 0) v += gw[n].x * __ldg(P + id[n].x);
            if (id[n].y >= 0) v += gw[n].y * __ldg(P + id[n].y);
            if (id[n].z >= 0) v += gw[n].z * __ldg(P + id[n].z);
            if (id[n].w >= 0) v += gw[n].w * __ldg(P + id[n].w);
            Sp[(size_t)n * HWF] = v;
        }
    }
}

// ---------------- deform conv (merged): 9 planes, 32 oc/block, 2 px/thread ----------------
__global__ void conv_s3_kernel(const float* __restrict__ wc_a, const float* __restrict__ wc_p) {
    __shared__ float SS[9][33][18];
    __shared__ float wS[9][32];
    int w0 = blockIdx.x * 16, h0 = blockIdx.y * 32;
    int bz = blockIdx.z;
    int og = bz & 1;
    int f = (bz >> 1) & 1;
    int b = bz >> 2;
    const float* wc = f ? wc_p : wc_a;
    int tid = threadIdx.x;
    int tx = tid & 15, ty = tid >> 4;
    u64 acc0[16], acc1[16];
#pragma unroll
    for (int j = 0; j < 16; j++) { acc0[j] = pack2(0.f, 0.f); acc1[j] = pack2(0.f, 0.f); }

    const int ni[3] = {2, 0, 1};
    const int dd[3] = {-1, 0, 0};
    const float* Sbr = g_S + (size_t)f * SBR;

    for (int ic = 0; ic < CC; ic++) {
        __syncthreads();
        const float* Sb = Sbr + ((size_t)(b * CC + ic) * 9) * HWF;
        for (int idx = tid; idx < 9 * 33 * 18; idx += 256) {
            int n = idx / 594;
            int rem = idx - n * 594;
            int rr = rem / 18, cc = rem - rr * 18;
            int gh = h0 - 1 + rr, gw = w0 - 1 + cc;
            SS[n][rr][cc] = (gh >= 0 && gh < HH && gw >= 0 && gw < WF)
                            ? Sb[(size_t)n * HWF + gh * WF + gw] : 0.f;
        }
        for (int idx = tid; idx < 9 * 32; idx += 256) {
            int k = idx >> 5, o = idx & 31;
            wS[k][o] = wc[((og * 32 + o) * CC + ic) * 9 + k];
        }
        __syncthreads();
#pragma unroll
        for (int rr = 0; rr < 3; rr++) {
#pragma unroll
            for (int c3 = 0; c3 < 3; c3++) {
                int n = ni[rr] * 3 + ni[c3];
                int row = 2 * ty + 1 + dd[rr];
                int col = tx + 1 + dd[c3];
                float v0 = SS[n][row][col];
                float v1 = SS[n][row + 1][col];
                u64 V0 = pack2(v0, v0);
                u64 V1 = pack2(v1, v1);
                int k = rr * 3 + c3;
#pragma unroll
                for (int j = 0; j < 16; j++) {
                    u64 Wv = *reinterpret_cast<const u64*>(&wS[k][2 * j]);
                    fma2(acc0[j], Wv, V0);
                    fma2(acc1[j], Wv, V1);
                }
            }
        }
    }
    int oh = h0 + 2 * ty, ow = w0 + tx;
    if (ow < WF) {
        float* dst = f ? g_p3 : g_a3;
#pragma unroll
        for (int j = 0; j < 16; j++) {
            float lo0, hi0, lo1, hi1;
            unpack2(acc0[j], lo0, hi0);
            unpack2(acc1[j], lo1, hi1);
            int oc = og * 32 + 2 * j;
            dst[((size_t)(b * CC + oc    ) * HH + oh) * WF + ow]     = lo0;
            dst[((size_t)(b * CC + oc + 1) * HH + oh) * WF + ow]     = hi0;
            dst[((size_t)(b * CC + oc    ) * HH + oh + 1) * WF + ow] = lo1;
            dst[((size_t)(b * CC + oc + 1) * HH + oh + 1) * WF + ow] = hi1;
        }
    }
}

// ---------------- 1x1 conv (merged) ----------------
__global__ void conv1x1_kernel(const float* __restrict__ w1_a, const float* __restrict__ b1_a,
                               const float* __restrict__ w1_p, const float* __restrict__ b1_p) {
    __shared__ float XS[64][33];
    __shared__ float WT[64][65];
    int p0 = blockIdx.x * 32;
    int by = blockIdx.y;
    int f = by & 1, b = by >> 1;
    const float* w1 = f ? w1_p : w1_a;
    const float* b1 = f ? b1_p : b1_a;
    int tid = threadIdx.x;
    const float* src = (f ? g_pha : g_amp) + (size_t)b * CC * HWF;
    for (int idx = tid; idx < 2048; idx += 256) {
        int c = idx >> 5, p = idx & 31;
        XS[c][p] = src[(size_t)c * HWF + p0 + p];
    }
    for (int idx = tid; idx < 4096; idx += 256) {
        int oc = idx >> 6, k = idx & 63;
        WT[k][oc] = w1[idx];
    }
    __syncthreads();
    int px = tid & 31, ocg = tid >> 5;
    float acc[8] = {0.f, 0.f, 0.f, 0.f, 0.f, 0.f, 0.f, 0.f};
    for (int k = 0; k < 64; k++) {
        float xv = XS[k][px];
#pragma unroll
        for (int j = 0; j < 8; j++) acc[j] += WT[k][ocg + 8 * j] * xv;
    }
    float* dst = (f ? g_p1 : g_a1) + (size_t)b * CC * HWF;
#pragma unroll
    for (int j = 0; j < 8; j++) {
        int oc = ocg + 8 * j;
        dst[(size_t)oc * HWF + p0 + px] = acc[j] + b1[oc];
    }
}

// ---------------- recombine ----------------
__global__ void combine_kernel() {
    size_t idx = (size_t)blockIdx.x * 256 + threadIdx.x;
    if (idx >= (size_t)NPIX) return;
    float a1 = g_a1[idx], p1 = g_p1[idx];
    float a3 = g_a3[idx], p3 = g_p3[idx];
    float s1, c1, s3, c3;
    sincos_acc(p1, &s1, &c1);
    sincos_acc(p3, &s3, &c3);
    g_XF[idx] = make_float2(a1 * c3 + a3 * c1 + 3e-8f,
                            a3 * s1 + a1 * s3 + 2e-8f);
}

// ---------------- final 5x5 conv: 16 oc packed, 2x2 px/thread, 4-ic batch ----------------
__global__ void conv5x5_kernel(const float* __restrict__ w0, const float* __restrict__ b0,
                               float* __restrict__ out) {
    __shared__ float T[4 * 36 * 37];
    __shared__ float wS[4][25][16];
    int w0b = blockIdx.x * 32, h0 = blockIdx.y * 32;
    int bz = blockIdx.z;
    int og = bz & 3;
    int b = bz >> 2;
    int tid = threadIdx.x;
    int tx = tid & 15, ty = tid >> 4;
    u64 acc00[8], acc01[8], acc10[8], acc11[8];
#pragma unroll
    for (int j = 0; j < 8; j++) {
        acc00[j] = pack2(0.f, 0.f); acc01[j] = pack2(0.f, 0.f);
        acc10[j] = pack2(0.f, 0.f); acc11[j] = pack2(0.f, 0.f);
    }

    for (int ic0 = 0; ic0 < CC; ic0 += 4) {
        __syncthreads();
        for (int idx = tid; idx < 4 * 1296; idx += 256) {
            int ii = idx / 1296;
            int rem = idx - ii * 1296;
            int r = rem / 36, cc = rem - r * 36;
            int gh = h0 + r - 2, gw = w0b + cc - 2;
            const float* P = g_xr + (size_t)(b * CC + ic0 + ii) * HH * WW;
            T[ii * 1332 + r * 37 + cc] = (gh >= 0 && gh < HH && gw >= 0 && gw < WW)
                                         ? P[(size_t)gh * WW + gw] : 0.f;
        }
        for (int idx = tid; idx < 1600; idx += 256) {
            int ii = idx / 400;
            int rem = idx - ii * 400;
            int k = rem / 16, o = rem - k * 16;
            wS[ii][k][o] = w0[((og * 16 + o) * CC + ic0 + ii) * 25 + k];
        }
        __syncthreads();
#pragma unroll
        for (int ii = 0; ii < 4; ii++) {
            const float* Tb = &T[ii * 1332];
#pragma unroll
            for (int k = 0; k < 25; k++) {
                int ky = k / 5, kx = k % 5;
                const float* row0 = Tb + (2 * ty + ky) * 37 + 2 * tx + kx;
                float v00 = row0[0];
                float v01 = row0[1];
                float v10 = row0[37];
                float v11 = row0[38];
                u64 V00 = pack2(v00, v00);
                u64 V01 = pack2(v01, v01);
                u64 V10 = pack2(v10, v10);
                u64 V11 = pack2(v11, v11);
#pragma unroll
                for (int j = 0; j < 8; j++) {
                    u64 Wv = *reinterpret_cast<const u64*>(&wS[ii][k][2 * j]);
                    fma2(acc00[j], Wv, V00);
                    fma2(acc01[j], Wv, V01);
                    fma2(acc10[j], Wv, V10);
                    fma2(acc11[j], Wv, V11);
                }
            }
        }
    }
    int h = h0 + 2 * ty, w = w0b + 2 * tx;
#pragma unroll
    for (int j = 0; j < 8; j++) {
        int oc = og * 16 + 2 * j;
        float l00, h00, l01, h01, l10, h10, l11, h11;
        unpack2(acc00[j], l00, h00);
        unpack2(acc01[j], l01, h01);
        unpack2(acc10[j], l10, h10);
        unpack2(acc11[j], l11, h11);
        float blo = b0[oc], bhi = b0[oc + 1];
        float* o0 = out + ((size_t)(b * CC + oc) * HH + h) * WW + w;
        float* o1 = out + ((size_t)(b * CC + oc + 1) * HH + h) * WW + w;
        o0[0] = l00 + blo;  o0[1] = l01 + blo;
        o0[WW] = l10 + blo; o0[WW + 1] = l11 + blo;
        o1[0] = h00 + bhi;  o1[1] = h01 + bhi;
        o1[WW] = h10 + bhi; o1[WW + 1] = h11 + bhi;
    }
}

// ---------------- launcher ----------------
extern "C" void kernel_launch(void* const* d_in, const int* in_sizes, int n_in,
                              void* d_out, int out_size) {
    (void)in_sizes; (void)n_in; (void)out_size;
    const float* x    = (const float*)d_in[0];
    const float* wp_a = (const float*)d_in[1];
    const float* bp_a = (const float*)d_in[2];
    const float* wc_a = (const float*)d_in[3];
    const float* w1_a = (const float*)d_in[4];
    const float* b1_a = (const float*)d_in[5];
    const float* wp_p = (const float*)d_in[6];
    const float* bp_p = (const float*)d_in[7];
    const float* wc_p = (const float*)d_in[8];
    const float* w1_p = (const float*)d_in[9];
    const float* b1_p = (const float*)d_in[10];
    const float* w0   = (const float*)d_in[11];
    const float* b0   = (const float*)d_in[12];
    float* out = (float*)d_out;

    twiddle_init<<<1, 129>>>();

    fft_row_fwd<<<BB * CC * HH, 128>>>(x);
    fft_col_kernel<<<dim3(9, CC, BB), 256>>>(0);

    // merged amp+pha deform pipeline
    conv_off_kernel<<<dim3(9, 8, BB * 2), 256>>>(wp_a, bp_a, wp_p, bp_p);
    sample_params_kernel<<<dim3((NP * 9 + 255) / 256, 2), 256>>>();
    gather_kernel<<<dim3((NP * 8 + 255) / 256, 2), 256>>>();
    conv_s3_kernel<<<dim3(9, 8, BB * 4), 256>>>(wc_a, wc_p);
    conv1x1_kernel<<<dim3(HWF / 32, BB * 2), 256>>>(w1_a, b1_a, w1_p, b1_p);

    // recombine + inverse transform
    combine_kernel<<<NPIX / 256, 256>>>();
    fft_col_kernel<<<dim3(9, CC, BB), 256>>>(1);
    ifft_row_kernel<<<BB * CC * HH, 128>>>();

    conv5x5_kernel<<<dim3(8, 8, BB * 4), 256>>>(w0, b0, out);
}

// round 7
// speedup vs baseline: 1.8334x; 1.2094x over previous
#include <cuda_runtime.h>
#include <math.h>

#define BB 4
#define CC 64
#define HH 256
#define WW 256
#define WF 129
#define HWF (HH*WF)            // 33024
#define NPIX (BB*CC*HWF)       // 8454144
#define NP (BB*HWF)            // 132096
#define FPAD 261

// ---------------- scratch (branch axis f: 0=amp, 1=pha) ----------------
__device__ float2 g_XF[NPIX];
__device__ float  g_amp[NPIX];
__device__ float  g_pha[NPIX];
__device__ float  g_a3[NPIX];
__device__ float  g_p3[NPIX];
__device__ float  g_offs[2*BB*18*HWF];
__device__ float  g_S[(size_t)2*BB*CC*9*HWF];   // sample planes [f][b][c][n][h][w]
__device__ float  g_xr[(size_t)BB*CC*HH*WW];
__device__ float2 g_tw[129];

#define SBR ((size_t)BB*CC*9*HWF)   // per-branch g_S stride

// ---------------- packed f32x2 helpers ----------------
typedef unsigned long long u64;
__device__ __forceinline__ u64 pack2(float lo, float hi) {
    u64 r; asm("mov.b64 %0, {%1, %2};" : "=l"(r) : "f"(lo), "f"(hi)); return r;
}
__device__ __forceinline__ void unpack2(u64 v, float& lo, float& hi) {
    asm("mov.b64 {%0, %1}, %2;" : "=f"(lo), "=f"(hi) : "l"(v));
}
__device__ __forceinline__ void fma2(u64& d, u64 a, u64 b) {
    asm("fma.rn.f32x2 %0, %1, %2, %0;" : "+l"(d) : "l"(a), "l"(b));
}

// ---------------- precise transcendentals ----------------
__device__ __forceinline__ void sincos_acc(float x, float* sp, float* cp) {
    float k = rintf(x * 0.63661977236758134f);
    float r = fmaf(k, -1.5707963705062866f, x);
    r = fmaf(k, 4.37113900018624e-8f, r);
    int q = (int)k;
    float z = r * r;
    float ss = 2.75573192e-6f;
    ss = fmaf(ss, z, -1.98412698e-4f);
    ss = fmaf(ss, z, 8.33333333e-3f);
    ss = fmaf(ss, z, -1.66666667e-1f);
    ss = fmaf(ss * z, r, r);
    float cc = -2.75573192e-7f;
    cc = fmaf(cc, z, 2.48015873e-5f);
    cc = fmaf(cc, z, -1.38888889e-3f);
    cc = fmaf(cc, z, 4.16666667e-2f);
    cc = fmaf(cc, z, -0.5f);
    cc = fmaf(cc, z, 1.0f);
    int qq = q & 3;
    float s_ = (qq & 1) ? cc : ss;
    float c_ = (qq & 1) ? ss : cc;
    if (qq == 1 || qq == 2) c_ = -c_;
    if (qq >= 2) s_ = -s_;
    *sp = s_; *cp = c_;
}

__device__ __forceinline__ float atan2_acc(float y, float x) {
    float ax = fabsf(x), ay = fabsf(y);
    float mx = fmaxf(ax, ay), mn = fminf(ax, ay);
    float t = (mx > 0.f) ? __fdiv_rn(mn, mx) : 0.f;
    float base = 0.f;
    if (t > 0.414213562f) { t = __fdiv_rn(t - 1.f, t + 1.f); base = 0.78539816339744831f; }
    float z = t * t;
    float p = -0.066666667f;
    p = fmaf(p, z,  0.076923077f);
    p = fmaf(p, z, -0.090909091f);
    p = fmaf(p, z,  0.111111111f);
    p = fmaf(p, z, -0.142857143f);
    p = fmaf(p, z,  0.2f);
    p = fmaf(p, z, -0.333333333f);
    float r = fmaf(t * z, p, t) + base;
    if (ay > ax) r = 1.57079632679489662f - r;
    if (x < 0.f) r = 3.14159265358979323f - r;
    return copysignf(r, y);
}

__global__ void twiddle_init() {
    int k = threadIdx.x;
    if (k < 129) {
        double a = -2.0 * 3.14159265358979323846 * (double)k / 256.0;
        float2 v = make_float2((float)cos(a), (float)sin(a));
        if (k == 0) v = make_float2(1.f, 0.f);
        g_tw[k] = v;
    }
}

// ---------------- FFT-256 (table = forward twiddles). sign=+1 fwd, -1 inv ----------------
__device__ __forceinline__ void fft256_tab(float2* s, const float2* tw, int t, float sign) {
#pragma unroll
    for (int kk = 0; kk < 2; kk++) {
        int i = t + (kk << 7);
        int j = __brev(i) >> 24;
        if (i < j) { float2 a = s[i]; s[i] = s[j]; s[j] = a; }
    }
    __syncthreads();
#pragma unroll
    for (int st = 1; st <= 8; st++) {
        int half = 1 << (st - 1);
        int g = t >> (st - 1);
        int p = t & (half - 1);
        int i0 = (g << st) + p;
        int i1 = i0 + half;
        float2 w = tw[p << (8 - st)];
        float wy = sign * w.y;
        float2 a = s[i0], b = s[i1];
        float2 wb = make_float2(w.x * b.x - wy * b.y, w.x * b.y + wy * b.x);
        s[i0] = make_float2(a.x + wb.x, a.y + wb.y);
        s[i1] = make_float2(a.x - wb.x, a.y - wb.y);
        __syncthreads();
    }
}

__global__ void fft_row_fwd(const float* __restrict__ x) {
    __shared__ float2 s[256];
    __shared__ float2 tw[128];
    int h = blockIdx.x & 255, bc = blockIdx.x >> 8, t = threadIdx.x;
    tw[t] = g_tw[t];
    const float* row = x + ((size_t)bc * 256 + h) * 256;
    s[t]       = make_float2(row[t], 0.f);
    s[t + 128] = make_float2(row[t + 128], 0.f);
    __syncthreads();
    fft256_tab(s, tw, t, +1.f);
    size_t ob = ((size_t)bc * 256 + h) * WF;
    g_XF[ob + t] = s[t];
    if (t == 0) g_XF[ob + 128] = s[128];
}

__global__ void fft_col_kernel(int dir) {
    __shared__ float2 S[16 * FPAD];
    __shared__ float2 tw[128];
    int k0 = blockIdx.x * 16;
    int c = blockIdx.y, b = blockIdx.z;
    int tid = threadIdx.x;
    if (tid < 128) tw[tid] = g_tw[tid];
    size_t base = ((size_t)(b * CC + c)) * HH * WF;

    for (int idx = tid; idx < 256 * 16; idx += 256) {
        int h = idx >> 4, kk = idx & 15;
        int k = k0 + kk;
        float2 v = (k < WF) ? g_XF[base + (size_t)h * WF + k] : make_float2(0.f, 0.f);
        S[kk * FPAD + h] = v;
    }
    __syncthreads();

    int f = tid >> 4;
    int l = tid & 15;
    float2* s = &S[f * FPAD];
#pragma unroll
    for (int m = 0; m < 16; m++) {
        int i = l + (m << 4);
        int j = __brev(i) >> 24;
        if (i < j) { float2 a = s[i]; s[i] = s[j]; s[j] = a; }
    }
    __syncthreads();
    float sign = dir ? -1.f : 1.f;
#pragma unroll
    for (int st = 1; st <= 8; st++) {
        int half = 1 << (st - 1);
#pragma unroll
        for (int m = 0; m < 8; m++) {
            int t = l + (m << 4);
            int g = t >> (st - 1);
            int p = t & (half - 1);
            int i0 = (g << st) + p;
            int i1 = i0 + half;
            float2 w = tw[p << (8 - st)];
            float wy = sign * w.y;
            float2 a = s[i0], bv = s[i1];
            float2 wb = make_float2(w.x * bv.x - wy * bv.y, w.x * bv.y + wy * bv.x);
            s[i0] = make_float2(a.x + wb.x, a.y + wb.y);
            s[i1] = make_float2(a.x - wb.x, a.y - wb.y);
        }
        __syncthreads();
    }

    if (dir == 0) {
        for (int idx = tid; idx < 256 * 16; idx += 256) {
            int h = idx >> 4, kk = idx & 15;
            int k = k0 + kk;
            if (k < WF) {
                float2 v = S[kk * FPAD + h];
                size_t o = base + (size_t)h * WF + k;
                g_amp[o] = __fsqrt_rn(fmaf(v.x, v.x, v.y * v.y));
                g_pha[o] = atan2_acc(v.y, v.x);
            }
        }
    } else {
        for (int idx = tid; idx < 256 * 16; idx += 256) {
            int h = idx >> 4, kk = idx & 15;
            int k = k0 + kk;
            if (k < WF) g_XF[base + (size_t)h * WF + k] = S[kk * FPAD + h];
        }
    }
}

__global__ void ifft_row_kernel() {
    __shared__ float2 s[256];
    __shared__ float2 tw[128];
    int h = blockIdx.x & 255, bc = blockIdx.x >> 8, t = threadIdx.x;
    tw[t] = g_tw[t];
    size_t base = ((size_t)bc * 256 + h) * WF;
    s[t] = g_XF[base + t];
    float2 v;
    if (t == 0) v = g_XF[base + 128];
    else { float2 u = g_XF[base + 128 - t]; v = make_float2(u.x, -u.y); }
    s[t + 128] = v;
    __syncthreads();
    fft256_tab(s, tw, t, -1.f);
    const float inv = 1.f / 65536.f;
    float* orow = g_xr + ((size_t)bc * 256 + h) * 256;
    orow[t]       = fabsf(s[t].x * inv);
    orow[t + 128] = fabsf(s[t + 128].x * inv);
}

// ------- merged 3x3 pad-1 conv 64->18, both branches, reg-prefetch pipeline -------
__global__ void __launch_bounds__(256, 3)
conv_off_kernel(const float* __restrict__ wp_a, const float* __restrict__ bp_a,
                const float* __restrict__ wp_p, const float* __restrict__ bp_p) {
    __shared__ float TT[612];    // 34 rows x 18 cols
    __shared__ float WS[162];    // [k][oc] 9x18
    int w0b = blockIdx.x * 16, h0 = blockIdx.y * 32;
    int bz = blockIdx.z;
    int f = bz & 1, b = bz >> 1;
    const float* src = f ? g_pha : g_amp;
    const float* wp = f ? wp_p : wp_a;
    const float* bp = f ? bp_p : bp_a;
    int tid = threadIdx.x;
    int tx = tid & 15, ty = tid >> 4;

    // precompute slot addressing (fixed per thread)
    int i0 = tid, i1 = tid + 256, i2 = tid + 512;
    bool v0, v1, v2;
    int o0, o1, o2;
    {
        int r, cc, gh, gw;
        r = i0 / 18; cc = i0 - r * 18; gh = h0 + r - 1; gw = w0b + cc - 1;
        v0 = (gh >= 0 && gh < HH && gw >= 0 && gw < WF); o0 = gh * WF + gw;
        r = i1 / 18; cc = i1 - r * 18; gh = h0 + r - 1; gw = w0b + cc - 1;
        v1 = (gh >= 0 && gh < HH && gw >= 0 && gw < WF); o1 = gh * WF + gw;
        r = i2 / 18; cc = i2 - r * 18; gh = h0 + r - 1; gw = w0b + cc - 1;
        v2 = (i2 < 612) && (gh >= 0 && gh < HH && gw >= 0 && gw < WF); o2 = gh * WF + gw;
    }
    bool wq = tid < 162;
    int wk = tid / 18, wo = tid % 18;
    int wbase = wo * CC * 9 + wk;     // + ic*9

    const float* P = src + (size_t)b * CC * HWF;
    // prefetch ic=0
    float rA = v0 ? __ldg(P + o0) : 0.f;
    float rB = v1 ? __ldg(P + o1) : 0.f;
    float rC = v2 ? __ldg(P + o2) : 0.f;
    float rW = wq ? __ldg(wp + wbase) : 0.f;

    u64 acc0[9], acc1[9];
#pragma unroll
    for (int j = 0; j < 9; j++) { acc0[j] = pack2(0.f, 0.f); acc1[j] = pack2(0.f, 0.f); }

    for (int ic = 0; ic < CC; ic++) {
        __syncthreads();
        TT[i0] = rA;
        TT[i1] = rB;
        if (i2 < 612) TT[i2] = rC;
        if (wq) WS[tid] = rW;
        if (ic < CC - 1) {
            const float* Pn = P + (size_t)(ic + 1) * HWF;
            rA = v0 ? __ldg(Pn + o0) : 0.f;
            rB = v1 ? __ldg(Pn + o1) : 0.f;
            rC = v2 ? __ldg(Pn + o2) : 0.f;
            rW = wq ? __ldg(wp + wbase + (ic + 1) * 9) : 0.f;
        }
        __syncthreads();
#pragma unroll
        for (int k = 0; k < 9; k++) {
            int ky = k / 3, kx = k % 3;
            float va = TT[(2 * ty + ky) * 18 + tx + kx];
            float vb = TT[(2 * ty + 1 + ky) * 18 + tx + kx];
            u64 V0 = pack2(va, va);
            u64 V1 = pack2(vb, vb);
#pragma unroll
            for (int j = 0; j < 9; j++) {
                u64 Wv = *reinterpret_cast<const u64*>(&WS[k * 18 + 2 * j]);
                fma2(acc0[j], Wv, V0);
                fma2(acc1[j], Wv, V1);
            }
        }
    }
    int h = h0 + 2 * ty, w = w0b + tx;
    if (w < WF) {
#pragma unroll
        for (int j = 0; j < 9; j++) {
            float lo0, hi0, lo1, hi1;
            unpack2(acc0[j], lo0, hi0);
            unpack2(acc1[j], lo1, hi1);
            float blo = bp[2 * j], bhi = bp[2 * j + 1];
            size_t base = (size_t)((f * BB + b) * 18);
            g_offs[((base + 2 * j    ) * HH + h) * WF + w]     = lo0 + blo;
            g_offs[((base + 2 * j + 1) * HH + h) * WF + w]     = hi0 + bhi;
            g_offs[((base + 2 * j    ) * HH + h + 1) * WF + w] = lo1 + blo;
            g_offs[((base + 2 * j + 1) * HH + h + 1) * WF + w] = hi1 + bhi;
        }
    }
}

// ---------------- fused sampling-params + gather: 1 thread per (f,b,h,w), all 64 ch ----------------
__device__ __forceinline__ int padidx(float qx, float qy) {
    int X = (int)qx, Y = (int)qy;
    if (X >= 1 && X <= 256 && Y >= 1 && Y <= 129) return (X - 1) * WF + (Y - 1);
    return -1;
}

__global__ void gather_kernel() {
    int t = blockIdx.x * 256 + threadIdx.x;
    if (t >= NP) return;
    int f = blockIdx.y;
    int w = t % WF;
    int r = t / WF;
    int h = r % HH;
    int b = r / HH;

    const float* Pb = (f ? g_pha : g_amp) + (size_t)b * CC * HWF;
    float* Sbase = g_S + (size_t)f * SBR + ((size_t)b * CC * 9) * HWF + (size_t)h * WF + w;
    size_t obase = (size_t)((f * BB + b) * 18);
    const float HMax = 257.f, WMax = 130.f;

#pragma unroll
    for (int n = 0; n < 9; n++) {
        int i = n / 3, j = n % 3;
        float offx = g_offs[((obase + n    ) * HH + h) * WF + w];
        float offy = g_offs[((obase + n + 9) * HH + h) * WF + w];
        float px = (float)(h + 1) + (float)(i - 1) + offx;
        float py = (float)(w + 1) + (float)(j - 1) + offy;
        float qx = floorf(px), qy = floorf(py);
        float qltx = fminf(fmaxf(qx, 0.f), HMax);
        float qlty = fminf(fmaxf(qy, 0.f), WMax);
        float qrbx = fminf(fmaxf(qx + 1.f, 0.f), HMax);
        float qrby = fminf(fmaxf(qy + 1.f, 0.f), WMax);
        float cpx  = fminf(fmaxf(px, 0.f), HMax);
        float cpy  = fminf(fmaxf(py, 0.f), WMax);
        float glt = (1.f + (qltx - cpx)) * (1.f + (qlty - cpy));
        float grb = (1.f - (qrbx - cpx)) * (1.f - (qrby - cpy));
        float glb = (1.f + (qltx - cpx)) * (1.f - (qrby - cpy));
        float grt = (1.f - (qrbx - cpx)) * (1.f + (qlty - cpy));
        int ilt = padidx(qltx, qlty);
        int irb = padidx(qrbx, qrby);
        int ilb = padidx(qltx, qrby);
        int irt = padidx(qrbx, qlty);
        float* Sn = Sbase + (size_t)n * HWF;
#pragma unroll 4
        for (int c = 0; c < CC; c++) {
            const float* P = Pb + (size_t)c * HWF;
            float v = 0.f;
            if (ilt >= 0) v += glt * __ldg(P + ilt);
            if (irb >= 0) v += grb * __ldg(P + irb);
            if (ilb >= 0) v += glb * __ldg(P + ilb);
            if (irt >= 0) v += grt * __ldg(P + irt);
            Sn[(size_t)c * 9 * HWF] = v;
        }
    }
}

// ---------------- deform conv (merged): 9 planes, 32 oc/block, 2 px/thread ----------------
__global__ void conv_s3_kernel(const float* __restrict__ wc_a, const float* __restrict__ wc_p) {
    __shared__ float SS[9][33][18];
    __shared__ float wS[9][32];
    int w0 = blockIdx.x * 16, h0 = blockIdx.y * 32;
    int bz = blockIdx.z;
    int og = bz & 1;
    int f = (bz >> 1) & 1;
    int b = bz >> 2;
    const float* wc = f ? wc_p : wc_a;
    int tid = threadIdx.x;
    int tx = tid & 15, ty = tid >> 4;
    u64 acc0[16], acc1[16];
#pragma unroll
    for (int j = 0; j < 16; j++) { acc0[j] = pack2(0.f, 0.f); acc1[j] = pack2(0.f, 0.f); }

    const int ni[3] = {2, 0, 1};
    const int dd[3] = {-1, 0, 0};
    const float* Sbr = g_S + (size_t)f * SBR;

    for (int ic = 0; ic < CC; ic++) {
        __syncthreads();
        const float* Sb = Sbr + ((size_t)(b * CC + ic) * 9) * HWF;
        for (int idx = tid; idx < 9 * 33 * 18; idx += 256) {
            int n = idx / 594;
            int rem = idx - n * 594;
            int rr = rem / 18, cc = rem - rr * 18;
            int gh = h0 - 1 + rr, gw = w0 - 1 + cc;
            SS[n][rr][cc] = (gh >= 0 && gh < HH && gw >= 0 && gw < WF)
                            ? Sb[(size_t)n * HWF + gh * WF + gw] : 0.f;
        }
        for (int idx = tid; idx < 9 * 32; idx += 256) {
            int k = idx >> 5, o = idx & 31;
            wS[k][o] = wc[((og * 32 + o) * CC + ic) * 9 + k];
        }
        __syncthreads();
#pragma unroll
        for (int rr = 0; rr < 3; rr++) {
#pragma unroll
            for (int c3 = 0; c3 < 3; c3++) {
                int n = ni[rr] * 3 + ni[c3];
                int row = 2 * ty + 1 + dd[rr];
                int col = tx + 1 + dd[c3];
                float v0 = SS[n][row][col];
                float v1 = SS[n][row + 1][col];
                u64 V0 = pack2(v0, v0);
                u64 V1 = pack2(v1, v1);
                int k = rr * 3 + c3;
#pragma unroll
                for (int j = 0; j < 16; j++) {
                    u64 Wv = *reinterpret_cast<const u64*>(&wS[k][2 * j]);
                    fma2(acc0[j], Wv, V0);
                    fma2(acc1[j], Wv, V1);
                }
            }
        }
    }
    int oh = h0 + 2 * ty, ow = w0 + tx;
    if (ow < WF) {
        float* dst = f ? g_p3 : g_a3;
#pragma unroll
        for (int j = 0; j < 16; j++) {
            float lo0, hi0, lo1, hi1;
            unpack2(acc0[j], lo0, hi0);
            unpack2(acc1[j], lo1, hi1);
            int oc = og * 32 + 2 * j;
            dst[((size_t)(b * CC + oc    ) * HH + oh) * WF + ow]     = lo0;
            dst[((size_t)(b * CC + oc + 1) * HH + oh) * WF + ow]     = hi0;
            dst[((size_t)(b * CC + oc    ) * HH + oh + 1) * WF + ow] = lo1;
            dst[((size_t)(b * CC + oc + 1) * HH + oh + 1) * WF + ow] = hi1;
        }
    }
}

// ---------------- fused conv1x1(both branches) + combine ----------------
extern __shared__ float dynC[];
__global__ void combine1x1_kernel(const float* __restrict__ w1_a, const float* __restrict__ b1_a,
                                  const float* __restrict__ w1_p, const float* __restrict__ b1_p) {
    float* XSa = dynC;                 // [64][33]
    float* XSp = XSa + 64 * 33;        // [64][33]
    float* WTa = XSp + 64 * 33;        // [k][oc] 64x64
    float* WTp = WTa + 64 * 64;        // [k][oc] 64x64
    int p0 = blockIdx.x * 32;
    int b = blockIdx.y;
    int tid = threadIdx.x;
    const float* sa = g_amp + (size_t)b * CC * HWF;
    const float* sp = g_pha + (size_t)b * CC * HWF;
    for (int idx = tid; idx < 2048; idx += 256) {
        int c = idx >> 5, p = idx & 31;
        XSa[c * 33 + p] = sa[(size_t)c * HWF + p0 + p];
        XSp[c * 33 + p] = sp[(size_t)c * HWF + p0 + p];
    }
    for (int idx = tid; idx < 4096; idx += 256) {
        int oc = idx >> 6, k = idx & 63;
        WTa[k * 64 + oc] = w1_a[idx];
        WTp[k * 64 + oc] = w1_p[idx];
    }
    __syncthreads();
    int px = tid & 31, ocg = tid >> 5;
    float a1acc[8] = {0.f, 0.f, 0.f, 0.f, 0.f, 0.f, 0.f, 0.f};
    float p1acc[8] = {0.f, 0.f, 0.f, 0.f, 0.f, 0.f, 0.f, 0.f};
    for (int k = 0; k < 64; k++) {
        float xa = XSa[k * 33 + px];
        float xp = XSp[k * 33 + px];
#pragma unroll
        for (int j = 0; j < 8; j++) {
            a1acc[j] = fmaf(WTa[k * 64 + ocg + 8 * j], xa, a1acc[j]);
            p1acc[j] = fmaf(WTp[k * 64 + ocg + 8 * j], xp, p1acc[j]);
        }
    }
#pragma unroll
    for (int j = 0; j < 8; j++) {
        int oc = ocg + 8 * j;
        float a1 = a1acc[j] + b1_a[oc];
        float p1 = p1acc[j] + b1_p[oc];
        size_t o = (size_t)(b * CC + oc) * HWF + p0 + px;
        float a3 = g_a3[o], p3 = g_p3[o];
        float s1, c1, s3, c3;
        sincos_acc(p1, &s1, &c1);
        sincos_acc(p3, &s3, &c3);
        g_XF[o] = make_float2(a1 * c3 + a3 * c1 + 3e-8f,
                              a3 * s1 + a1 * s3 + 2e-8f);
    }
}

// ---------------- final 5x5 conv: 16 oc packed, 2x2 px/thread, 8-ic batch ----------------
extern __shared__ float dyn5[];
__global__ void conv5x5_kernel(const float* __restrict__ w0, const float* __restrict__ b0,
                               float* __restrict__ out) {
    float* T  = dyn5;                 // 8 x [36][37]
    float* wS = dyn5 + 8 * 1332;      // 8 x [25][16]
    int w0b = blockIdx.x * 32, h0 = blockIdx.y * 32;
    int bz = blockIdx.z;
    int og = bz & 3;
    int b = bz >> 2;
    int tid = threadIdx.x;
    int tx = tid & 15, ty = tid >> 4;
    u64 acc00[8], acc01[8], acc10[8], acc11[8];
#pragma unroll
    for (int j = 0; j < 8; j++) {
        acc00[j] = pack2(0.f, 0.f); acc01[j] = pack2(0.f, 0.f);
        acc10[j] = pack2(0.f, 0.f); acc11[j] = pack2(0.f, 0.f);
    }

    for (int ic0 = 0; ic0 < CC; ic0 += 8) {
        __syncthreads();
        for (int idx = tid; idx < 8 * 1296; idx += 256) {
            int ii = idx / 1296;
            int rem = idx - ii * 1296;
            int r = rem / 36, cc = rem - r * 36;
            int gh = h0 + r - 2, gw = w0b + cc - 2;
            const float* P = g_xr + (size_t)(b * CC + ic0 + ii) * HH * WW;
            T[ii * 1332 + r * 37 + cc] = (gh >= 0 && gh < HH && gw >= 0 && gw < WW)
                                         ? P[(size_t)gh * WW + gw] : 0.f;
        }
        for (int idx = tid; idx < 3200; idx += 256) {
            int ii = idx / 400;
            int rem = idx - ii * 400;
            int k = rem / 16, o = rem - k * 16;
            wS[ii * 400 + k * 16 + o] = w0[((og * 16 + o) * CC + ic0 + ii) * 25 + k];
        }
        __syncthreads();
#pragma unroll
        for (int ii = 0; ii < 8; ii++) {
            const float* Tb = &T[ii * 1332];
            const float* Wb = &wS[ii * 400];
#pragma unroll
            for (int k = 0; k < 25; k++) {
                int ky = k / 5, kx = k % 5;
                const float* row0 = Tb + (2 * ty + ky) * 37 + 2 * tx + kx;
                float v00 = row0[0];
                float v01 = row0[1];
                float v10 = row0[37];
                float v11 = row0[38];
                u64 V00 = pack2(v00, v00);
                u64 V01 = pack2(v01, v01);
                u64 V10 = pack2(v10, v10);
                u64 V11 = pack2(v11, v11);
#pragma unroll
                for (int j = 0; j < 8; j++) {
                    u64 Wv = *reinterpret_cast<const u64*>(&Wb[k * 16 + 2 * j]);
                    fma2(acc00[j], Wv, V00);
                    fma2(acc01[j], Wv, V01);
                    fma2(acc10[j], Wv, V10);
                    fma2(acc11[j], Wv, V11);
                }
            }
        }
    }
    int h = h0 + 2 * ty, w = w0b + 2 * tx;
#pragma unroll
    for (int j = 0; j < 8; j++) {
        int oc = og * 16 + 2 * j;
        float l00, h00, l01, h01, l10, h10, l11, h11;
        unpack2(acc00[j], l00, h00);
        unpack2(acc01[j], l01, h01);
        unpack2(acc10[j], l10, h10);
        unpack2(acc11[j], l11, h11);
        float blo = b0[oc], bhi = b0[oc + 1];
        float* o0 = out + ((size_t)(b * CC + oc) * HH + h) * WW + w;
        float* o1 = out + ((size_t)(b * CC + oc + 1) * HH + h) * WW + w;
        o0[0] = l00 + blo;  o0[1] = l01 + blo;
        o0[WW] = l10 + blo; o0[WW + 1] = l11 + blo;
        o1[0] = h00 + bhi;  o1[1] = h01 + bhi;
        o1[WW] = h10 + bhi; o1[WW + 1] = h11 + bhi;
    }
}

// ---------------- launcher ----------------
extern "C" void kernel_launch(void* const* d_in, const int* in_sizes, int n_in,
                              void* d_out, int out_size) {
    (void)in_sizes; (void)n_in; (void)out_size;
    const float* x    = (const float*)d_in[0];
    const float* wp_a = (const float*)d_in[1];
    const float* bp_a = (const float*)d_in[2];
    const float* wc_a = (const float*)d_in[3];
    const float* w1_a = (const float*)d_in[4];
    const float* b1_a = (const float*)d_in[5];
    const float* wp_p = (const float*)d_in[6];
    const float* bp_p = (const float*)d_in[7];
    const float* wc_p = (const float*)d_in[8];
    const float* w1_p = (const float*)d_in[9];
    const float* b1_p = (const float*)d_in[10];
    const float* w0   = (const float*)d_in[11];
    const float* b0   = (const float*)d_in[12];
    float* out = (float*)d_out;

    static int attr_done = 0;
    if (!attr_done) {
        cudaFuncSetAttribute(combine1x1_kernel, cudaFuncAttributeMaxDynamicSharedMemorySize, 49664);
        cudaFuncSetAttribute(conv5x5_kernel, cudaFuncAttributeMaxDynamicSharedMemorySize, 55424);
        attr_done = 1;
    }

    twiddle_init<<<1, 129>>>();

    fft_row_fwd<<<BB * CC * HH, 128>>>(x);
    fft_col_kernel<<<dim3(9, CC, BB), 256>>>(0);

    // merged amp+pha deform pipeline
    conv_off_kernel<<<dim3(9, 8, BB * 2), 256>>>(wp_a, bp_a, wp_p, bp_p);
    gather_kernel<<<dim3(NP / 256, 2), 256>>>();
    conv_s3_kernel<<<dim3(9, 8, BB * 4), 256>>>(wc_a, wc_p);

    // fused 1x1 conv + recombine, then inverse transform
    combine1x1_kernel<<<dim3(HWF / 32, BB), 256, 49664>>>(w1_a, b1_a, w1_p, b1_p);
    fft_col_kernel<<<dim3(9, CC, BB), 256>>>(1);
    ifft_row_kernel<<<BB * CC * HH, 128>>>();

    conv5x5_kernel<<<dim3(8, 8, BB * 4), 256, 55424>>>(w0, b0, out);
}

// round 9
// speedup vs baseline: 2.1178x; 1.1551x over previous
#include <cuda_runtime.h>
#include <stdint.h>
#include <math.h>

#define BB 4
#define CC 64
#define HH 256
#define WW 256
#define WF 129
#define HWF (HH*WF)            // 33024
#define NPIX (BB*CC*HWF)       // 8454144
#define NP (BB*HWF)            // 132096
#define FPAD 261

// ---------------- scratch (branch axis f: 0=amp, 1=pha) ----------------
__device__ float2 g_XF[NPIX];
__device__ float  g_amp[NPIX];
__device__ float  g_pha[NPIX];
__device__ float  g_a3[NPIX];
__device__ float  g_p3[NPIX];
__device__ float  g_offs[2*BB*18*HWF];
__device__ float  g_S[(size_t)2*BB*CC*9*HWF];   // sample planes [f][b][c][n][h][w]
__device__ float  g_xr[(size_t)BB*CC*HH*WW];
__device__ float2 g_tw[129];

#define SBR ((size_t)BB*CC*9*HWF)   // per-branch g_S stride

// ---------------- packed f32x2 helpers ----------------
typedef unsigned long long u64;
__device__ __forceinline__ u64 pack2(float lo, float hi) {
    u64 r; asm("mov.b64 %0, {%1, %2};" : "=l"(r) : "f"(lo), "f"(hi)); return r;
}
__device__ __forceinline__ void unpack2(u64 v, float& lo, float& hi) {
    asm("mov.b64 {%0, %1}, %2;" : "=f"(lo), "=f"(hi) : "l"(v));
}
__device__ __forceinline__ void fma2(u64& d, u64 a, u64 b) {
    asm("fma.rn.f32x2 %0, %1, %2, %0;" : "+l"(d) : "l"(a), "l"(b));
}

// ---------------- cp.async helpers ----------------
__device__ __forceinline__ void cpa4(uint32_t dst, const float* src, bool pred) {
    int sz = pred ? 4 : 0;
    asm volatile("cp.async.ca.shared.global [%0], [%1], 4, %2;" :: "r"(dst), "l"(src), "r"(sz));
}
#define CP_COMMIT() asm volatile("cp.async.commit_group;" ::: "memory")
#define CP_WAIT1()  asm volatile("cp.async.wait_group 1;" ::: "memory")
#define CP_WAIT0()  asm volatile("cp.async.wait_group 0;" ::: "memory")

// ---------------- precise transcendentals ----------------
__device__ __forceinline__ void sincos_acc(float x, float* sp, float* cp) {
    float k = rintf(x * 0.63661977236758134f);
    float r = fmaf(k, -1.5707963705062866f, x);
    r = fmaf(k, 4.37113900018624e-8f, r);
    int q = (int)k;
    float z = r * r;
    float ss = 2.75573192e-6f;
    ss = fmaf(ss, z, -1.98412698e-4f);
    ss = fmaf(ss, z, 8.33333333e-3f);
    ss = fmaf(ss, z, -1.66666667e-1f);
    ss = fmaf(ss * z, r, r);
    float cc = -2.75573192e-7f;
    cc = fmaf(cc, z, 2.48015873e-5f);
    cc = fmaf(cc, z, -1.38888889e-3f);
    cc = fmaf(cc, z, 4.16666667e-2f);
    cc = fmaf(cc, z, -0.5f);
    cc = fmaf(cc, z, 1.0f);
    int qq = q & 3;
    float s_ = (qq & 1) ? cc : ss;
    float c_ = (qq & 1) ? ss : cc;
    if (qq == 1 || qq == 2) c_ = -c_;
    if (qq >= 2) s_ = -s_;
    *sp = s_; *cp = c_;
}

__device__ __forceinline__ float atan2_acc(float y, float x) {
    float ax = fabsf(x), ay = fabsf(y);
    float mx = fmaxf(ax, ay), mn = fminf(ax, ay);
    float t = (mx > 0.f) ? __fdiv_rn(mn, mx) : 0.f;
    float base = 0.f;
    if (t > 0.414213562f) { t = __fdiv_rn(t - 1.f, t + 1.f); base = 0.78539816339744831f; }
    float z = t * t;
    float p = -0.066666667f;
    p = fmaf(p, z,  0.076923077f);
    p = fmaf(p, z, -0.090909091f);
    p = fmaf(p, z,  0.111111111f);
    p = fmaf(p, z, -0.142857143f);
    p = fmaf(p, z,  0.2f);
    p = fmaf(p, z, -0.333333333f);
    float r = fmaf(t * z, p, t) + base;
    if (ay > ax) r = 1.57079632679489662f - r;
    if (x < 0.f) r = 3.14159265358979323f - r;
    return copysignf(r, y);
}

__global__ void twiddle_init() {
    int k = threadIdx.x;
    if (k < 129) {
        double a = -2.0 * 3.14159265358979323846 * (double)k / 256.0;
        float2 v = make_float2((float)cos(a), (float)sin(a));
        if (k == 0) v = make_float2(1.f, 0.f);
        g_tw[k] = v;
    }
}

// ---------------- FFT-256 (table = forward twiddles). sign=+1 fwd, -1 inv ----------------
__device__ __forceinline__ void fft256_tab(float2* s, const float2* tw, int t, float sign) {
#pragma unroll
    for (int kk = 0; kk < 2; kk++) {
        int i = t + (kk << 7);
        int j = __brev(i) >> 24;
        if (i < j) { float2 a = s[i]; s[i] = s[j]; s[j] = a; }
    }
    __syncthreads();
#pragma unroll
    for (int st = 1; st <= 8; st++) {
        int half = 1 << (st - 1);
        int g = t >> (st - 1);
        int p = t & (half - 1);
        int i0 = (g << st) + p;
        int i1 = i0 + half;
        float2 w = tw[p << (8 - st)];
        float wy = sign * w.y;
        float2 a = s[i0], b = s[i1];
        float2 wb = make_float2(w.x * b.x - wy * b.y, w.x * b.y + wy * b.x);
        s[i0] = make_float2(a.x + wb.x, a.y + wb.y);
        s[i1] = make_float2(a.x - wb.x, a.y - wb.y);
        __syncthreads();
    }
}

__global__ void fft_row_fwd(const float* __restrict__ x) {
    __shared__ float2 s[256];
    __shared__ float2 tw[128];
    int h = blockIdx.x & 255, bc = blockIdx.x >> 8, t = threadIdx.x;
    tw[t] = g_tw[t];
    const float* row = x + ((size_t)bc * 256 + h) * 256;
    s[t]       = make_float2(row[t], 0.f);
    s[t + 128] = make_float2(row[t + 128], 0.f);
    __syncthreads();
    fft256_tab(s, tw, t, +1.f);
    size_t ob = ((size_t)bc * 256 + h) * WF;
    g_XF[ob + t] = s[t];
    if (t == 0) g_XF[ob + 128] = s[128];
}

__global__ void fft_col_kernel(int dir) {
    __shared__ float2 S[16 * FPAD];
    __shared__ float2 tw[128];
    int k0 = blockIdx.x * 16;
    int c = blockIdx.y, b = blockIdx.z;
    int tid = threadIdx.x;
    if (tid < 128) tw[tid] = g_tw[tid];
    size_t base = ((size_t)(b * CC + c)) * HH * WF;

    for (int idx = tid; idx < 256 * 16; idx += 256) {
        int h = idx >> 4, kk = idx & 15;
        int k = k0 + kk;
        float2 v = (k < WF) ? g_XF[base + (size_t)h * WF + k] : make_float2(0.f, 0.f);
        S[kk * FPAD + h] = v;
    }
    __syncthreads();

    int f = tid >> 4;
    int l = tid & 15;
    float2* s = &S[f * FPAD];
#pragma unroll
    for (int m = 0; m < 16; m++) {
        int i = l + (m << 4);
        int j = __brev(i) >> 24;
        if (i < j) { float2 a = s[i]; s[i] = s[j]; s[j] = a; }
    }
    __syncthreads();
    float sign = dir ? -1.f : 1.f;
#pragma unroll
    for (int st = 1; st <= 8; st++) {
        int half = 1 << (st - 1);
#pragma unroll
        for (int m = 0; m < 8; m++) {
            int t = l + (m << 4);
            int g = t >> (st - 1);
            int p = t & (half - 1);
            int i0 = (g << st) + p;
            int i1 = i0 + half;
            float2 w = tw[p << (8 - st)];
            float wy = sign * w.y;
            float2 a = s[i0], bv = s[i1];
            float2 wb = make_float2(w.x * bv.x - wy * bv.y, w.x * bv.y + wy * bv.x);
            s[i0] = make_float2(a.x + wb.x, a.y + wb.y);
            s[i1] = make_float2(a.x - wb.x, a.y - wb.y);
        }
        __syncthreads();
    }

    if (dir == 0) {
        for (int idx = tid; idx < 256 * 16; idx += 256) {
            int h = idx >> 4, kk = idx & 15;
            int k = k0 + kk;
            if (k < WF) {
                float2 v = S[kk * FPAD + h];
                size_t o = base + (size_t)h * WF + k;
                g_amp[o] = __fsqrt_rn(fmaf(v.x, v.x, v.y * v.y));
                g_pha[o] = atan2_acc(v.y, v.x);
            }
        }
    } else {
        for (int idx = tid; idx < 256 * 16; idx += 256) {
            int h = idx >> 4, kk = idx & 15;
            int k = k0 + kk;
            if (k < WF) g_XF[base + (size_t)h * WF + k] = S[kk * FPAD + h];
        }
    }
}

__global__ void ifft_row_kernel() {
    __shared__ float2 s[256];
    __shared__ float2 tw[128];
    int h = blockIdx.x & 255, bc = blockIdx.x >> 8, t = threadIdx.x;
    tw[t] = g_tw[t];
    size_t base = ((size_t)bc * 256 + h) * WF;
    s[t] = g_XF[base + t];
    float2 v;
    if (t == 0) v = g_XF[base + 128];
    else { float2 u = g_XF[base + 128 - t]; v = make_float2(u.x, -u.y); }
    s[t + 128] = v;
    __syncthreads();
    fft256_tab(s, tw, t, -1.f);
    const float inv = 1.f / 65536.f;
    float* orow = g_xr + ((size_t)bc * 256 + h) * 256;
    orow[t]       = fabsf(s[t].x * inv);
    orow[t + 128] = fabsf(s[t + 128].x * inv);
}

// ------- merged 3x3 pad-1 conv 64->18, cp.async double-buffered -------
__global__ void __launch_bounds__(256, 3)
conv_off_kernel(const float* __restrict__ wp_a, const float* __restrict__ bp_a,
                const float* __restrict__ wp_p, const float* __restrict__ bp_p) {
    __shared__ float TT[2][612];    // 34 rows x 18 cols
    __shared__ float WS[2][162];    // [k][oc]
    int w0b = blockIdx.x * 16, h0 = blockIdx.y * 32;
    int bz = blockIdx.z;
    int f = bz & 1, b = bz >> 1;
    const float* src = f ? g_pha : g_amp;
    const float* wp = f ? wp_p : wp_a;
    const float* bp = f ? bp_p : bp_a;
    int tid = threadIdx.x;
    int tx = tid & 15, ty = tid >> 4;

    // per-thread slots (ic-invariant)
    int i0 = tid, i1 = tid + 256, i2 = tid + 512;
    bool v0, v1, v2;
    int o0, o1, o2;
    {
        int r, cc, gh, gw;
        r = i0 / 18; cc = i0 - r * 18; gh = h0 + r - 1; gw = w0b + cc - 1;
        v0 = (gh >= 0 && gh < HH && gw >= 0 && gw < WF); o0 = gh * WF + gw;
        r = i1 / 18; cc = i1 - r * 18; gh = h0 + r - 1; gw = w0b + cc - 1;
        v1 = (gh >= 0 && gh < HH && gw >= 0 && gw < WF); o1 = gh * WF + gw;
        r = i2 / 18; cc = i2 - r * 18; gh = h0 + r - 1; gw = w0b + cc - 1;
        v2 = (i2 < 612) && (gh >= 0 && gh < HH && gw >= 0 && gw < WF); o2 = gh * WF + gw;
    }
    bool wq = tid < 162;
    int wbase = (tid % 18) * CC * 9 + tid / 18;     // + ic*9
    const float* P = src + (size_t)b * CC * HWF;

    uint32_t tb[2], wb2[2];
    tb[0] = (uint32_t)__cvta_generic_to_shared(&TT[0][0]);
    tb[1] = (uint32_t)__cvta_generic_to_shared(&TT[1][0]);
    wb2[0] = (uint32_t)__cvta_generic_to_shared(&WS[0][0]);
    wb2[1] = (uint32_t)__cvta_generic_to_shared(&WS[1][0]);

    // prologue: stage 0
    {
        const float* Pn = P;
        cpa4(tb[0] + 4u * i0, Pn + o0, v0);
        cpa4(tb[0] + 4u * i1, Pn + o1, v1);
        if (i2 < 612) cpa4(tb[0] + 4u * i2, Pn + o2, v2);
        if (wq) cpa4(wb2[0] + 4u * tid, wp + wbase, true);
        CP_COMMIT();
    }

    u64 acc0[9], acc1[9];
#pragma unroll
    for (int j = 0; j < 9; j++) { acc0[j] = pack2(0.f, 0.f); acc1[j] = pack2(0.f, 0.f); }

    for (int ic = 0; ic < CC; ic++) {
        int cur = ic & 1;
        if (ic + 1 < CC) {
            int nxt = cur ^ 1;
            const float* Pn = P + (size_t)(ic + 1) * HWF;
            cpa4(tb[nxt] + 4u * i0, Pn + o0, v0);
            cpa4(tb[nxt] + 4u * i1, Pn + o1, v1);
            if (i2 < 612) cpa4(tb[nxt] + 4u * i2, Pn + o2, v2);
            if (wq) cpa4(wb2[nxt] + 4u * tid, wp + wbase + (ic + 1) * 9, true);
            CP_COMMIT();
            CP_WAIT1();
        } else {
            CP_WAIT0();
        }
        __syncthreads();
        const float* Tc = &TT[cur][0];
        const float* Wc = &WS[cur][0];
#pragma unroll
        for (int k = 0; k < 9; k++) {
            int ky = k / 3, kx = k % 3;
            float va = Tc[(2 * ty + ky) * 18 + tx + kx];
            float vb = Tc[(2 * ty + 1 + ky) * 18 + tx + kx];
            u64 V0 = pack2(va, va);
            u64 V1 = pack2(vb, vb);
#pragma unroll
            for (int j = 0; j < 9; j++) {
                u64 Wv = *reinterpret_cast<const u64*>(&Wc[k * 18 + 2 * j]);
                fma2(acc0[j], Wv, V0);
                fma2(acc1[j], Wv, V1);
            }
        }
        __syncthreads();
    }
    int h = h0 + 2 * ty, w = w0b + tx;
    if (w < WF) {
#pragma unroll
        for (int j = 0; j < 9; j++) {
            float lo0, hi0, lo1, hi1;
            unpack2(acc0[j], lo0, hi0);
            unpack2(acc1[j], lo1, hi1);
            float blo = bp[2 * j], bhi = bp[2 * j + 1];
            size_t base = (size_t)((f * BB + b) * 18);
            g_offs[((base + 2 * j    ) * HH + h) * WF + w]     = lo0 + blo;
            g_offs[((base + 2 * j + 1) * HH + h) * WF + w]     = hi0 + bhi;
            g_offs[((base + 2 * j    ) * HH + h + 1) * WF + w] = lo1 + blo;
            g_offs[((base + 2 * j + 1) * HH + h + 1) * WF + w] = hi1 + bhi;
        }
    }
}

// ---------------- fused sampling-params + gather ----------------
__device__ __forceinline__ int padidx(float qx, float qy) {
    int X = (int)qx, Y = (int)qy;
    if (X >= 1 && X <= 256 && Y >= 1 && Y <= 129) return (X - 1) * WF + (Y - 1);
    return -1;
}

__global__ void gather_kernel() {
    int t = blockIdx.x * 256 + threadIdx.x;
    if (t >= NP) return;
    int f = blockIdx.y;
    int w = t % WF;
    int r = t / WF;
    int h = r % HH;
    int b = r / HH;

    const float* Pb = (f ? g_pha : g_amp) + (size_t)b * CC * HWF;
    float* Sbase = g_S + (size_t)f * SBR + ((size_t)b * CC * 9) * HWF + (size_t)h * WF + w;
    size_t obase = (size_t)((f * BB + b) * 18);
    const float HMax = 257.f, WMax = 130.f;

#pragma unroll
    for (int n = 0; n < 9; n++) {
        int i = n / 3, j = n % 3;
        float offx = g_offs[((obase + n    ) * HH + h) * WF + w];
        float offy = g_offs[((obase + n + 9) * HH + h) * WF + w];
        float px = (float)(h + 1) + (float)(i - 1) + offx;
        float py = (float)(w + 1) + (float)(j - 1) + offy;
        float qx = floorf(px), qy = floorf(py);
        float qltx = fminf(fmaxf(qx, 0.f), HMax);
        float qlty = fminf(fmaxf(qy, 0.f), WMax);
        float qrbx = fminf(fmaxf(qx + 1.f, 0.f), HMax);
        float qrby = fminf(fmaxf(qy + 1.f, 0.f), WMax);
        float cpx  = fminf(fmaxf(px, 0.f), HMax);
        float cpy  = fminf(fmaxf(py, 0.f), WMax);
        float glt = (1.f + (qltx - cpx)) * (1.f + (qlty - cpy));
        float grb = (1.f - (qrbx - cpx)) * (1.f - (qrby - cpy));
        float glb = (1.f + (qltx - cpx)) * (1.f - (qrby - cpy));
        float grt = (1.f - (qrbx - cpx)) * (1.f + (qlty - cpy));
        int ilt = padidx(qltx, qlty);
        int irb = padidx(qrbx, qrby);
        int ilb = padidx(qltx, qrby);
        int irt = padidx(qrbx, qlty);
        float* Sn = Sbase + (size_t)n * HWF;
#pragma unroll 4
        for (int c = 0; c < CC; c++) {
            const float* P = Pb + (size_t)c * HWF;
            float v = 0.f;
            if (ilt >= 0) v += glt * __ldg(P + ilt);
            if (irb >= 0) v += grb * __ldg(P + irb);
            if (ilb >= 0) v += glb * __ldg(P + ilb);
            if (irt >= 0) v += grt * __ldg(P + irt);
            Sn[(size_t)c * 9 * HWF] = v;
        }
    }
}

// ------- deform conv (merged): cp.async double-buffered, 32 oc/block, 2 px/thread -------
__global__ void conv_s3_kernel(const float* __restrict__ wc_a, const float* __restrict__ wc_p) {
    __shared__ float SS[2][5346];    // 9 planes x 33 x 18
    __shared__ float WSS[2][288];
    int w0 = blockIdx.x * 16, h0 = blockIdx.y * 32;
    int bz = blockIdx.z;
    int og = bz & 1;
    int f = (bz >> 1) & 1;
    int b = bz >> 2;
    const float* wc = f ? wc_p : wc_a;
    int tid = threadIdx.x;
    int tx = tid & 15, ty = tid >> 4;
    u64 acc0[16], acc1[16];
#pragma unroll
    for (int j = 0; j < 16; j++) { acc0[j] = pack2(0.f, 0.f); acc1[j] = pack2(0.f, 0.f); }

    const int ni[3] = {2, 0, 1};
    const int dd[3] = {-1, 0, 0};
    const float* Sbr = g_S + (size_t)f * SBR + ((size_t)b * CC * 9) * HWF;

    // per-thread in-plane slots (plane-invariant)
    int poff[3]; bool ppred[3];
#pragma unroll
    for (int u = 0; u < 3; u++) {
        int idx2 = tid + (u << 8);
        int rr = idx2 / 18, cc = idx2 - rr * 18;
        int gh = h0 - 1 + rr, gw = w0 - 1 + cc;
        ppred[u] = (idx2 < 594) && (gh >= 0 && gh < HH && gw >= 0 && gw < WF);
        poff[u] = gh * WF + gw;
    }
    // weight slots: 288 elems
    int wo0 = ((og * 32 + (tid & 31)) * CC) * 9 + (tid >> 5);
    int idxw1 = tid + 256;
    int wo1 = ((og * 32 + (idxw1 & 31)) * CC) * 9 + (idxw1 >> 5);
    bool wp1 = idxw1 < 288;

    uint32_t tb[2], wb2[2];
    tb[0] = (uint32_t)__cvta_generic_to_shared(&SS[0][0]);
    tb[1] = (uint32_t)__cvta_generic_to_shared(&SS[1][0]);
    wb2[0] = (uint32_t)__cvta_generic_to_shared(&WSS[0][0]);
    wb2[1] = (uint32_t)__cvta_generic_to_shared(&WSS[1][0]);

    // stage loader
    auto load_stage = [&](int ic, int bufi) {
        const float* Sb = Sbr + (size_t)ic * 9 * HWF;
#pragma unroll
        for (int n = 0; n < 9; n++) {
            const float* Pn = Sb + (size_t)n * HWF;
            uint32_t dbs = tb[bufi] + 4u * (n * 594);
#pragma unroll
            for (int u = 0; u < 3; u++) {
                int idx2 = tid + (u << 8);
                if (idx2 < 594) cpa4(dbs + 4u * idx2, Pn + poff[u], ppred[u]);
            }
        }
        cpa4(wb2[bufi] + 4u * tid, wc + wo0 + ic * 9, true);
        if (wp1) cpa4(wb2[bufi] + 4u * idxw1, wc + wo1 + ic * 9, true);
    };

    load_stage(0, 0);
    CP_COMMIT();

    for (int ic = 0; ic < CC; ic++) {
        int cur = ic & 1;
        if (ic + 1 < CC) {
            load_stage(ic + 1, cur ^ 1);
            CP_COMMIT();
            CP_WAIT1();
        } else {
            CP_WAIT0();
        }
        __syncthreads();
        const float* Sc = &SS[cur][0];
        const float* Wc = &WSS[cur][0];
#pragma unroll
        for (int rr = 0; rr < 3; rr++) {
#pragma unroll
            for (int c3 = 0; c3 < 3; c3++) {
                int n = ni[rr] * 3 + ni[c3];
                int row = 2 * ty + 1 + dd[rr];
                int col = tx + 1 + dd[c3];
                float v0 = Sc[n * 594 + row * 18 + col];
                float v1 = Sc[n * 594 + (row + 1) * 18 + col];
                u64 V0 = pack2(v0, v0);
                u64 V1 = pack2(v1, v1);
                int k = rr * 3 + c3;
#pragma unroll
                for (int j = 0; j < 16; j++) {
                    u64 Wv = *reinterpret_cast<const u64*>(&Wc[k * 32 + 2 * j]);
                    fma2(acc0[j], Wv, V0);
                    fma2(acc1[j], Wv, V1);
                }
            }
        }
        __syncthreads();
    }
    int oh = h0 + 2 * ty, ow = w0 + tx;
    if (ow < WF) {
        float* dst = f ? g_p3 : g_a3;
#pragma unroll
        for (int j = 0; j < 16; j++) {
            float lo0, hi0, lo1, hi1;
            unpack2(acc0[j], lo0, hi0);
            unpack2(acc1[j], lo1, hi1);
            int oc = og * 32 + 2 * j;
            dst[((size_t)(b * CC + oc    ) * HH + oh) * WF + ow]     = lo0;
            dst[((size_t)(b * CC + oc + 1) * HH + oh) * WF + ow]     = hi0;
            dst[((size_t)(b * CC + oc    ) * HH + oh + 1) * WF + ow] = lo1;
            dst[((size_t)(b * CC + oc + 1) * HH + oh + 1) * WF + ow] = hi1;
        }
    }
}

// ---------------- fused conv1x1(both branches) + combine ----------------
extern __shared__ float dynC[];
__global__ void combine1x1_kernel(const float* __restrict__ w1_a, const float* __restrict__ b1_a,
                                  const float* __restrict__ w1_p, const float* __restrict__ b1_p) {
    float* XSa = dynC;
    float* XSp = XSa + 64 * 33;
    float* WTa = XSp + 64 * 33;
    float* WTp = WTa + 64 * 64;
    int p0 = blockIdx.x * 32;
    int b = blockIdx.y;
    int tid = threadIdx.x;
    const float* sa = g_amp + (size_t)b * CC * HWF;
    const float* sp = g_pha + (size_t)b * CC * HWF;
    for (int idx = tid; idx < 2048; idx += 256) {
        int c = idx >> 5, p = idx & 31;
        XSa[c * 33 + p] = sa[(size_t)c * HWF + p0 + p];
        XSp[c * 33 + p] = sp[(size_t)c * HWF + p0 + p];
    }
    for (int idx = tid; idx < 4096; idx += 256) {
        int oc = idx >> 6, k = idx & 63;
        WTa[k * 64 + oc] = w1_a[idx];
        WTp[k * 64 + oc] = w1_p[idx];
    }
    __syncthreads();
    int px = tid & 31, ocg = tid >> 5;
    float a1acc[8] = {0.f, 0.f, 0.f, 0.f, 0.f, 0.f, 0.f, 0.f};
    float p1acc[8] = {0.f, 0.f, 0.f, 0.f, 0.f, 0.f, 0.f, 0.f};
    for (int k = 0; k < 64; k++) {
        float xa = XSa[k * 33 + px];
        float xp = XSp[k * 33 + px];
#pragma unroll
        for (int j = 0; j < 8; j++) {
            a1acc[j] = fmaf(WTa[k * 64 + ocg + 8 * j], xa, a1acc[j]);
            p1acc[j] = fmaf(WTp[k * 64 + ocg + 8 * j], xp, p1acc[j]);
        }
    }
#pragma unroll
    for (int j = 0; j < 8; j++) {
        int oc = ocg + 8 * j;
        float a1 = a1acc[j] + b1_a[oc];
        float p1 = p1acc[j] + b1_p[oc];
        size_t o = (size_t)(b * CC + oc) * HWF + p0 + px;
        float a3 = g_a3[o], p3 = g_p3[o];
        float s1, c1, s3, c3;
        sincos_acc(p1, &s1, &c1);
        sincos_acc(p3, &s3, &c3);
        g_XF[o] = make_float2(a1 * c3 + a3 * c1 + 3e-8f,
                              a3 * s1 + a1 * s3 + 2e-8f);
    }
}

// ------- final 5x5 conv: cp.async double-buffered, 16 oc packed, 2x2 px, 8-ic batch -------
extern __shared__ float dyn5[];
__global__ void conv5x5_kernel(const float* __restrict__ w0, const float* __restrict__ b0,
                               float* __restrict__ out) {
    float* T0 = dyn5;                      // 8 x 1332
    float* T1 = T0 + 8 * 1332;
    float* W0b = T1 + 8 * 1332;            // 3200
    float* W1b = W0b + 3200;
    int w0b = blockIdx.x * 32, h0 = blockIdx.y * 32;
    int bz = blockIdx.z;
    int og = bz & 3;
    int b = bz >> 2;
    int tid = threadIdx.x;
    int tx = tid & 15, ty = tid >> 4;
    u64 acc00[8], acc01[8], acc10[8], acc11[8];
#pragma unroll
    for (int j = 0; j < 8; j++) {
        acc00[j] = pack2(0.f, 0.f); acc01[j] = pack2(0.f, 0.f);
        acc10[j] = pack2(0.f, 0.f); acc11[j] = pack2(0.f, 0.f);
    }

    // per-thread in-plane slots: 1296 elems/plane
    int poff[6], pdst[6]; bool ppred[6];
#pragma unroll
    for (int u = 0; u < 6; u++) {
        int idx2 = tid + (u << 8);
        int rr = idx2 / 36, cc = idx2 - rr * 36;
        int gh = h0 + rr - 2, gw = w0b + cc - 2;
        ppred[u] = (idx2 < 1296) && (gh >= 0 && gh < HH && gw >= 0 && gw < WW);
        poff[u] = gh * WW + gw;
        pdst[u] = rr * 37 + cc;
    }
    // weight slots: 400 per plane
    int wk0 = tid / 16, wo0 = tid % 16;
    int idxw1 = tid + 256;
    int wk1 = idxw1 / 16, wo1 = idxw1 % 16;
    bool wpq1 = idxw1 < 400;
    int wbase0 = ((og * 16 + wo0) * CC) * 25 + wk0;
    int wbase1 = ((og * 16 + wo1) * CC) * 25 + wk1;

    const float* Pb = g_xr + (size_t)(b * CC) * HH * WW;
    uint32_t tb[2], wb2[2];
    tb[0] = (uint32_t)__cvta_generic_to_shared(T0);
    tb[1] = (uint32_t)__cvta_generic_to_shared(T1);
    wb2[0] = (uint32_t)__cvta_generic_to_shared(W0b);
    wb2[1] = (uint32_t)__cvta_generic_to_shared(W1b);

    auto load_stage = [&](int ic0, int bufi) {
#pragma unroll
        for (int ii = 0; ii < 8; ii++) {
            const float* Pn = Pb + (size_t)(ic0 + ii) * HH * WW;
            uint32_t dbs = tb[bufi] + 4u * (ii * 1332);
#pragma unroll
            for (int u = 0; u < 6; u++) {
                int idx2 = tid + (u << 8);
                if (idx2 < 1296) cpa4(dbs + 4u * pdst[u], Pn + poff[u], ppred[u]);
            }
            uint32_t wdbs = wb2[bufi] + 4u * (ii * 400);
            cpa4(wdbs + 4u * tid, w0 + wbase0 + (ic0 + ii) * 25, true);
            if (wpq1) cpa4(wdbs + 4u * idxw1, w0 + wbase1 + (ic0 + ii) * 25, true);
        }
    };

    load_stage(0, 0);
    CP_COMMIT();

    for (int s = 0; s < 8; s++) {
        int cur = s & 1;
        if (s + 1 < 8) {
            load_stage((s + 1) * 8, cur ^ 1);
            CP_COMMIT();
            CP_WAIT1();
        } else {
            CP_WAIT0();
        }
        __syncthreads();
        const float* Tc = cur ? T1 : T0;
        const float* Wc = cur ? W1b : W0b;
#pragma unroll
        for (int ii = 0; ii < 8; ii++) {
            const float* Tb = &Tc[ii * 1332];
            const float* Wb = &Wc[ii * 400];
#pragma unroll
            for (int k = 0; k < 25; k++) {
                int ky = k / 5, kx = k % 5;
                const float* row0 = Tb + (2 * ty + ky) * 37 + 2 * tx + kx;
                float v00 = row0[0];
                float v01 = row0[1];
                float v10 = row0[37];
                float v11 = row0[38];
                u64 V00 = pack2(v00, v00);
                u64 V01 = pack2(v01, v01);
                u64 V10 = pack2(v10, v10);
                u64 V11 = pack2(v11, v11);
#pragma unroll
                for (int j = 0; j < 8; j++) {
                    u64 Wv = *reinterpret_cast<const u64*>(&Wb[k * 16 + 2 * j]);
                    fma2(acc00[j], Wv, V00);
                    fma2(acc01[j], Wv, V01);
                    fma2(acc10[j], Wv, V10);
                    fma2(acc11[j], Wv, V11);
                }
            }
        }
        __syncthreads();
    }
    int h = h0 + 2 * ty, w = w0b + 2 * tx;
#pragma unroll
    for (int j = 0; j < 8; j++) {
        int oc = og * 16 + 2 * j;
        float l00, h00, l01, h01, l10, h10, l11, h11;
        unpack2(acc00[j], l00, h00);
        unpack2(acc01[j], l01, h01);
        unpack2(acc10[j], l10, h10);
        unpack2(acc11[j], l11, h11);
        float blo = b0[oc], bhi = b0[oc + 1];
        float* o0 = out + ((size_t)(b * CC + oc) * HH + h) * WW + w;
        float* o1 = out + ((size_t)(b * CC + oc + 1) * HH + h) * WW + w;
        o0[0] = l00 + blo;  o0[1] = l01 + blo;
        o0[WW] = l10 + blo; o0[WW + 1] = l11 + blo;
        o1[0] = h00 + bhi;  o1[1] = h01 + bhi;
        o1[WW] = h10 + bhi; o1[WW + 1] = h11 + bhi;
    }
}

// ---------------- launcher ----------------
extern "C" void kernel_launch(void* const* d_in, const int* in_sizes, int n_in,
                              void* d_out, int out_size) {
    (void)in_sizes; (void)n_in; (void)out_size;
    const float* x    = (const float*)d_in[0];
    const float* wp_a = (const float*)d_in[1];
    const float* bp_a = (const float*)d_in[2];
    const float* wc_a = (const float*)d_in[3];
    const float* w1_a = (const float*)d_in[4];
    const float* b1_a = (const float*)d_in[5];
    const float* wp_p = (const float*)d_in[6];
    const float* bp_p = (const float*)d_in[7];
    const float* wc_p = (const float*)d_in[8];
    const float* w1_p = (const float*)d_in[9];
    const float* b1_p = (const float*)d_in[10];
    const float* w0   = (const float*)d_in[11];
    const float* b0   = (const float*)d_in[12];
    float* out = (float*)d_out;

    static int attr_done = 0;
    if (!attr_done) {
        cudaFuncSetAttribute(combine1x1_kernel, cudaFuncAttributeMaxDynamicSharedMemorySize, 49664);
        cudaFuncSetAttribute(conv5x5_kernel, cudaFuncAttributeMaxDynamicSharedMemorySize, 110848);
        attr_done = 1;
    }

    twiddle_init<<<1, 129>>>();

    fft_row_fwd<<<BB * CC * HH, 128>>>(x);
    fft_col_kernel<<<dim3(9, CC, BB), 256>>>(0);

    // merged amp+pha deform pipeline
    conv_off_kernel<<<dim3(9, 8, BB * 2), 256>>>(wp_a, bp_a, wp_p, bp_p);
    gather_kernel<<<dim3(NP / 256, 2), 256>>>();
    conv_s3_kernel<<<dim3(9, 8, BB * 4), 256>>>(wc_a, wc_p);

    // fused 1x1 conv + recombine, then inverse transform
    combine1x1_kernel<<<dim3(HWF / 32, BB), 256, 49664>>>(w1_a, b1_a, w1_p, b1_p);
    fft_col_kernel<<<dim3(9, CC, BB), 256>>>(1);
    ifft_row_kernel<<<BB * CC * HH, 128>>>();

    conv5x5_kernel<<<dim3(8, 8, BB * 4), 256, 110848>>>(w0, b0, out);
}